// round 13
// baseline (speedup 1.0000x reference)
#include <cuda_runtime.h>
#include <cuda_bf16.h>
#include <math.h>
#include <stdint.h>

#define BB 2
#define SS 2048
#define DD 1024
#define HH 16
#define DK 64
#define MROWS (BB*SS)   // 4096

// Scratch (device globals — allocation is forbidden)
__device__ float g_qlin[MROWS*DD];
__device__ float g_klin[MROWS*DD];
__device__ float g_vlin[MROWS*DD];
__device__ float g_cos[SS*32];
__device__ float g_sin[SS*32];
// bf16-split packed operands for flash: u32 = packed bf16x2
__device__ uint32_t g_qh[BB*HH*SS*32];
__device__ uint32_t g_ql[BB*HH*SS*32];
__device__ uint32_t g_kh[BB*HH*SS*32];
__device__ uint32_t g_kl[BB*HH*SS*32];
__device__ uint32_t g_vh[BB*HH*(SS/2)*DK];
__device__ uint32_t g_vl[BB*HH*(SS/2)*DK];
// bf16-split packed GEMM operands, CHUNK-MAJOR blocked: [chunk64][rows][8 u32]
__device__ uint32_t g_ah[3][MROWS*512];
__device__ uint32_t g_al[3][MROWS*512];
__device__ uint32_t g_wh[4][DD*512];
__device__ uint32_t g_wl[4][DD*512];
__device__ uint32_t g_cth[MROWS*512];
__device__ uint32_t g_ctl[MROWS*512];

// ---------------------------------------------------------------------------
__device__ __forceinline__ uint32_t pack_hi(float a, float b, float& ra, float& rb)
{
    __nv_bfloat16 ha = __float2bfloat16(a);
    __nv_bfloat16 hb = __float2bfloat16(b);
    ra = a - __bfloat162float(ha);
    rb = b - __bfloat162float(hb);
    __nv_bfloat162 p;
    p.x = ha; p.y = hb;
    return *reinterpret_cast<uint32_t*>(&p);
}
__device__ __forceinline__ uint32_t pack_lo(float ra, float rb)
{
    __nv_bfloat162 p = __floats2bfloat162_rn(ra, rb);
    return *reinterpret_cast<uint32_t*>(&p);
}
__device__ __forceinline__ float ex2(float x)
{
    float r;
    asm("ex2.approx.f32 %0, %1;" : "=f"(r) : "f"(x));
    return r;
}

#define MMA_BF16(d, a, b) \
    asm volatile("mma.sync.aligned.m16n8k16.row.col.f32.bf16.bf16.f32 " \
        "{%0,%1,%2,%3}, {%4,%5,%6,%7}, {%8,%9}, {%0,%1,%2,%3};" \
        : "+f"(d[0]), "+f"(d[1]), "+f"(d[2]), "+f"(d[3]) \
        : "r"(a[0]), "r"(a[1]), "r"(a[2]), "r"(a[3]), "r"(b[0]), "r"(b[1]))

#define CPA16(dst, src)    asm volatile("cp.async.cg.shared.global [%0], [%1], 16;" :: "r"(dst), "l"(src))
#define CPA16CA(dst, src)  asm volatile("cp.async.ca.shared.global [%0], [%1], 16;" :: "r"(dst), "l"(src))
#define CPA_COMMIT()       asm volatile("cp.async.commit_group;" ::: "memory")
#define CPA_WAIT(N)        asm volatile("cp.async.wait_group %0;" :: "n"(N) : "memory")

// ---------------------------------------------------------------------------
__global__ __launch_bounds__(256) void rope_tables(float* cosT, float* sinT)
{
    const int t = blockIdx.x * 256 + threadIdx.x;
    const int j = t & 31;
    const int s = t >> 5;
    double inv = exp(-(double)j * 0.28782313662425575);
    double sd, cd;
    sincos((double)s * inv, &sd, &cd);
    cosT[t] = (float)cd;
    sinT[t] = (float)sd;
}

// ---------------------------------------------------------------------------
// split_pack to CHUNK-MAJOR blocked layout: dst[(chunk*nrows + row)*8 + half*4]
// ---------------------------------------------------------------------------
__global__ __launch_bounds__(256) void split_pack3(
    const float* __restrict__ X0, const float* __restrict__ X1,
    const float* __restrict__ X2,
    uint32_t* __restrict__ Xh, uint32_t* __restrict__ Xl, size_t ostride)
{
    const float* X = (blockIdx.y == 0) ? X0 : ((blockIdx.y == 1) ? X1 : X2);
    uint32_t* H = Xh + blockIdx.y * ostride;
    uint32_t* L = Xl + blockIdx.y * ostride;
    const size_t t = (size_t)blockIdx.x * 256 + threadIdx.x;
    const int row   = (int)(t >> 7);
    const int rem   = (int)(t & 127);
    const int chunk = rem >> 1;
    const int half  = rem & 1;
    float4 v0 = ((const float4*)X)[2*t];
    float4 v1 = ((const float4*)X)[2*t+1];
    float r0, r1, r2, r3, r4, r5, r6, r7;
    uint4 h, l;
    h.x = pack_hi(v0.x, v0.y, r0, r1);
    h.y = pack_hi(v0.z, v0.w, r2, r3);
    h.z = pack_hi(v1.x, v1.y, r4, r5);
    h.w = pack_hi(v1.z, v1.w, r6, r7);
    l.x = pack_lo(r0, r1); l.y = pack_lo(r2, r3);
    l.z = pack_lo(r4, r5); l.w = pack_lo(r6, r7);
    const size_t d = ((size_t)chunk * MROWS + row) * 2 + half;
    ((uint4*)H)[d] = h;
    ((uint4*)L)[d] = l;
}

__global__ __launch_bounds__(256) void split_pack4(
    const float* __restrict__ X0, const float* __restrict__ X1,
    const float* __restrict__ X2, const float* __restrict__ X3,
    uint32_t* __restrict__ Xh, uint32_t* __restrict__ Xl, size_t ostride)
{
    const float* X = (blockIdx.y == 0) ? X0 : ((blockIdx.y == 1) ? X1 :
                     ((blockIdx.y == 2) ? X2 : X3));
    uint32_t* H = Xh + blockIdx.y * ostride;
    uint32_t* L = Xl + blockIdx.y * ostride;
    const size_t t = (size_t)blockIdx.x * 256 + threadIdx.x;
    const int row   = (int)(t >> 7);
    const int rem   = (int)(t & 127);
    const int chunk = rem >> 1;
    const int half  = rem & 1;
    float4 v0 = ((const float4*)X)[2*t];
    float4 v1 = ((const float4*)X)[2*t+1];
    float r0, r1, r2, r3, r4, r5, r6, r7;
    uint4 h, l;
    h.x = pack_hi(v0.x, v0.y, r0, r1);
    h.y = pack_hi(v0.z, v0.w, r2, r3);
    h.z = pack_hi(v1.x, v1.y, r4, r5);
    h.w = pack_hi(v1.z, v1.w, r6, r7);
    l.x = pack_lo(r0, r1); l.y = pack_lo(r2, r3);
    l.z = pack_lo(r4, r5); l.w = pack_lo(r6, r7);
    const size_t d = ((size_t)chunk * DD + row) * 2 + half;
    ((uint4*)H)[d] = h;
    ((uint4*)L)[d] = l;
}

// ---------------------------------------------------------------------------
// gemm_tc4: 128x128 tile, 8 warps (64x32), 3x-split bf16 MMA.
// Row-major pitch-12 smem (frag banks (12*qrow+qk)%32 all-distinct, proven R10)
// filled by cp.async.CA (L1-caching — .cg was the R10 regression) from
// chunk-major global (contiguous 32B per thread). 3-stage ring, 1 sync/iter,
// no STS, no register staging.
// Stage (u32, base s*6144): Ah@0, Al@1536, Wh@3072, Wl@4608; row*12 + k2.
// ---------------------------------------------------------------------------
#define GPITCH 12
#define GSTG 6144
#define GEMM_SMEM (3*GSTG*4)        // 73728 B
#define ACH 32768   // u32 per chunk in activation arrays
#define WCH 8192    // u32 per chunk in weight arrays

struct GArg {
    const uint32_t *ah, *al, *wh, *wl;
    const float* bias;
    float* c;
};

__global__ __launch_bounds__(256, 2) void gemm_tc4(GArg g0, GArg g1, GArg g2)
{
    extern __shared__ uint32_t gsm[];
    const uint32_t sbase = (uint32_t)__cvta_generic_to_shared(gsm);

    GArg g = (blockIdx.z == 0) ? g0 : ((blockIdx.z == 1) ? g1 : g2);
    const int tid = threadIdx.x;
    const int bm = blockIdx.y, bn = blockIdx.x;
    const int lane = tid & 31, wid = tid >> 5;
    const int wm = (wid >> 2) * 64;
    const int wn = (wid & 3) * 32;
    const int qrow = lane >> 2, qk = lane & 3;

    // loader: sel=0 -> A rows, sel=1 -> W rows; 8 u32 contiguous per chunk-row
    const int r   = tid & 127;
    const int sel = tid >> 7;
    const uint32_t* pH = sel ? g.wh + (size_t)(bn*128 + r)*8
                             : g.ah + (size_t)(bm*128 + r)*8;
    const uint32_t* pL = sel ? g.wl + (size_t)(bn*128 + r)*8
                             : g.al + (size_t)(bm*128 + r)*8;
    const size_t CH = sel ? (size_t)WCH : (size_t)ACH;
    const uint32_t dH = sbase + (sel*3072 + r*GPITCH)*4;
    const uint32_t dL = dH + 1536*4;

    float d[4][4][4];
    #pragma unroll
    for (int mt = 0; mt < 4; mt++)
        #pragma unroll
        for (int nt = 0; nt < 4; nt++)
            #pragma unroll
            for (int i = 0; i < 4; i++) d[mt][nt][i] = 0.f;

    // prologue: stages 0,1 = chunks 0,1
    #pragma unroll
    for (int p = 0; p < 2; p++) {
        const uint32_t sb = (uint32_t)(p*GSTG*4);
        const uint32_t* sh = pH + (size_t)p*CH;
        const uint32_t* sl = pL + (size_t)p*CH;
        CPA16CA(dH + sb,      sh);
        CPA16CA(dH + sb + 16, sh + 4);
        CPA16CA(dL + sb,      sl);
        CPA16CA(dL + sb + 16, sl + 4);
        CPA_COMMIT();
    }

    int s = 0;
    for (int c = 0; c < 64; c++) {
        if (c + 1 < 64) { CPA_WAIT(1); } else { CPA_WAIT(0); }
        __syncthreads();

        // issue chunk c+2 into stage (s+2)%3 (its readers finished in iter c-1)
        if (c + 2 < 64) {
            const int s2 = (s + 2 >= 3) ? (s - 1) : (s + 2);
            const uint32_t sb = (uint32_t)(s2*GSTG*4);
            const uint32_t* sh = pH + (size_t)(c+2)*CH;
            const uint32_t* sl = pL + (size_t)(c+2)*CH;
            CPA16CA(dH + sb,      sh);
            CPA16CA(dH + sb + 16, sh + 4);
            CPA16CA(dL + sb,      sl);
            CPA16CA(dL + sb + 16, sl + 4);
            CPA_COMMIT();
        }

        const uint32_t* S = gsm + s*GSTG;

        uint32_t afh[4][4], afl[4][4], bfh[4][2], bfl[4][2];
        #pragma unroll
        for (int mt = 0; mt < 4; mt++) {
            const int m0 = wm + mt*16 + qrow;
            #pragma unroll
            for (int i = 0; i < 4; i++) {
                const int m  = m0 + ((i & 1) << 3);
                const int k2 = qk + ((i >> 1) << 2);
                afh[mt][i] = S[m*GPITCH + k2];
                afl[mt][i] = S[1536 + m*GPITCH + k2];
            }
        }
        #pragma unroll
        for (int nt = 0; nt < 4; nt++) {
            const int n0 = wn + nt*8 + qrow;
            #pragma unroll
            for (int i = 0; i < 2; i++) {
                bfh[nt][i] = S[3072 + n0*GPITCH + qk + 4*i];
                bfl[nt][i] = S[4608 + n0*GPITCH + qk + 4*i];
            }
        }

        #pragma unroll
        for (int mt = 0; mt < 4; mt++)
            #pragma unroll
            for (int nt = 0; nt < 4; nt++) {
                MMA_BF16(d[mt][nt], afh[mt], bfh[nt]);
                MMA_BF16(d[mt][nt], afh[mt], bfl[nt]);
                MMA_BF16(d[mt][nt], afl[mt], bfh[nt]);
            }

        s = (s + 1 >= 3) ? 0 : (s + 1);
    }

    #pragma unroll
    for (int mt = 0; mt < 4; mt++)
        #pragma unroll
        for (int nt = 0; nt < 4; nt++) {
            int col0 = bn*128 + wn + nt*8 + 2*qk;
            float b0 = g.bias[col0], b1 = g.bias[col0+1];
            #pragma unroll
            for (int half = 0; half < 2; half++) {
                int row = bm*128 + wm + mt*16 + qrow + 8*half;
                float2 v;
                v.x = d[mt][nt][2*half+0] + b0;
                v.y = d[mt][nt][2*half+1] + b1;
                *(float2*)&g.c[(size_t)row*DD + col0] = v;
            }
        }
}

// ---------------------------------------------------------------------------
// RoPE + head-transpose + bf16 split for Q,K. Q scale = (1/8)*log2(e).
// ---------------------------------------------------------------------------
__global__ __launch_bounds__(256) void rope_split(
    const float* __restrict__ qlin, const float* __restrict__ klin,
    const float* __restrict__ cosT, const float* __restrict__ sinT,
    uint32_t* __restrict__ qh, uint32_t* __restrict__ ql,
    uint32_t* __restrict__ kh, uint32_t* __restrict__ kl)
{
    const int t = blockIdx.x * 256 + threadIdx.x;
    const float* src = blockIdx.y ? klin : qlin;
    uint32_t* dh = blockIdx.y ? kh : qh;
    uint32_t* dl = blockIdx.y ? kl : ql;
    const float scale = blockIdx.y ? 1.0f : 0.18033688011112042f;  // 0.125*log2(e)

    const int k2 = t & 15;
    const int s  = (t >> 4) & (SS - 1);
    const int bh = t >> 15;
    const int b = bh >> 4, h = bh & 15;
    const int j0 = 2*k2, j1 = 2*k2 + 1;

    const float* sp = src + ((size_t)(b*SS + s))*DD + h*DK;
    float x0 = sp[j0],      x1 = sp[j1];
    float y0 = sp[j0 + 32], y1 = sp[j1 + 32];
    float c0 = cosT[s*32 + j0], c1 = cosT[s*32 + j1];
    float s0 = sinT[s*32 + j0], s1 = sinT[s*32 + j1];

    float o0 = (x0*c0 - y0*s0) * scale;
    float o1 = (x1*c1 - y1*s1) * scale;
    float p0 = (y0*c0 + x0*s0) * scale;
    float p1 = (y1*c1 + x1*s1) * scale;

    size_t base = ((size_t)bh*SS + s)*32;
    float r0, r1;
    uint32_t hv = pack_hi(o0, o1, r0, r1);
    dh[base + k2] = hv;            dl[base + k2] = pack_lo(r0, r1);
    hv = pack_hi(p0, p1, r0, r1);
    dh[base + k2 + 16] = hv;       dl[base + k2 + 16] = pack_lo(r0, r1);
}

// ---------------------------------------------------------------------------
__global__ __launch_bounds__(256) void v_split(
    const float* __restrict__ vlin,
    uint32_t* __restrict__ vh, uint32_t* __restrict__ vl)
{
    const int t = blockIdx.x * 256 + threadIdx.x;
    const int d4 = (t & 15) * 4;
    const int kp = (t >> 4) & 1023;
    const int bh = t >> 14;
    const int b = bh >> 4, h = bh & 15;

    const float* r0p = vlin + ((size_t)(b*SS + 2*kp))*DD + h*DK + d4;
    float4 a = *(const float4*)r0p;
    float4 c = *(const float4*)(r0p + DD);

    uint32_t hh[4], ll[4];
    float ra, rb;
    hh[0] = pack_hi(a.x, c.x, ra, rb); ll[0] = pack_lo(ra, rb);
    hh[1] = pack_hi(a.y, c.y, ra, rb); ll[1] = pack_lo(ra, rb);
    hh[2] = pack_hi(a.z, c.z, ra, rb); ll[2] = pack_lo(ra, rb);
    hh[3] = pack_hi(a.w, c.w, ra, rb); ll[3] = pack_lo(ra, rb);

    size_t base = ((size_t)bh*1024 + kp)*64 + d4;
    *(uint4*)&vh[base] = make_uint4(hh[0], hh[1], hh[2], hh[3]);
    *(uint4*)&vl[base] = make_uint4(ll[0], ll[1], ll[2], ll[3]);
}

// ---------------------------------------------------------------------------
// Flash v5 (unchanged from R12): no-max softmax, cp.async.cg K/V double
// buffer, pass-major MMAs, chunk-major blocked ctx epilogue.
// ---------------------------------------------------------------------------
#define QP 36
#define VP 72
#define FLASH_SMEM (27648*4)

__global__ __launch_bounds__(256, 2) void flash_tc5(
    const uint32_t* __restrict__ qh_g, const uint32_t* __restrict__ ql_g,
    const uint32_t* __restrict__ kh_g, const uint32_t* __restrict__ kl_g,
    const uint32_t* __restrict__ vh_g, const uint32_t* __restrict__ vl_g,
    uint32_t* __restrict__ cth, uint32_t* __restrict__ ctl)
{
    extern __shared__ uint32_t smu[];
    const uint32_t sbase = (uint32_t)__cvta_generic_to_shared(smu);

    const int tid = threadIdx.x;
    const int qi = 15 - blockIdx.x;
    const int bh = blockIdx.y;
    const int b = bh >> 4, h = bh & 15;
    const int lane = tid & 31, wid = tid >> 5;
    const int qk = lane & 3, qrow = lane >> 2;
    const int wr = wid * 16;
    const int nkt = 2*qi + 2;

    const int krow = tid >> 2, kk2b = (tid & 3) * 8;
    const int vkp  = tid >> 3, vdb  = (tid & 7) * 8;
    const size_t kgo = ((size_t)bh*SS + krow)*32 + kk2b;
    const size_t vgo = ((size_t)bh*1024 + vkp)*64 + vdb;

    {
        const int row = tid >> 1, cb = (tid & 1) * 16;
        const uint32_t* sh = qh_g + ((size_t)bh*SS + qi*128 + row)*32 + cb;
        const uint32_t* sl = ql_g + ((size_t)bh*SS + qi*128 + row)*32 + cb;
        uint32_t dh = sbase + (row*QP + cb)*4;
        uint32_t dl = sbase + (4608 + row*QP + cb)*4;
        CPA16(dh,    sh);     CPA16(dh+16, sh+4);
        CPA16(dh+32, sh+8);   CPA16(dh+48, sh+12);
        CPA16(dl,    sl);     CPA16(dl+16, sl+4);
        CPA16(dl+32, sl+8);   CPA16(dl+48, sl+12);
    }
    CPA_COMMIT();

    #pragma unroll
    for (int pk = 0; pk < 2; pk++) {
        uint32_t kh_d = sbase + (9216  + pk*2304 + krow*QP + kk2b)*4;
        uint32_t kl_d = sbase + (13824 + pk*2304 + krow*QP + kk2b)*4;
        uint32_t vh_d = sbase + (18432 + pk*2304 + vkp*VP + vdb)*4;
        uint32_t vl_d = sbase + (23040 + pk*2304 + vkp*VP + vdb)*4;
        const uint32_t* skh = kh_g + kgo + (size_t)pk*64*32;
        const uint32_t* skl = kl_g + kgo + (size_t)pk*64*32;
        const uint32_t* svh = vh_g + vgo + (size_t)pk*32*64;
        const uint32_t* svl = vl_g + vgo + (size_t)pk*32*64;
        CPA16(kh_d, skh);  CPA16(kh_d+16, skh+4);
        CPA16(kl_d, skl);  CPA16(kl_d+16, skl+4);
        CPA16(vh_d, svh);  CPA16(vh_d+16, svh+4);
        CPA16(vl_d, svl);  CPA16(vl_d+16, svl+4);
        CPA_COMMIT();
    }

    float l0 = 0.f, l1 = 0.f;
    float of[8][4];
    #pragma unroll
    for (int nt = 0; nt < 8; nt++)
        #pragma unroll
        for (int i = 0; i < 4; i++) of[nt][i] = 0.f;

    const uint32_t* QhS = smu;
    const uint32_t* QlS = smu + 4608;

    for (int kt = 0; kt < nkt; kt++) {
        const int st = kt & 1;
        if (kt + 1 < nkt) { CPA_WAIT(1); } else { CPA_WAIT(0); }
        __syncthreads();

        const uint32_t* KhS = smu + 9216  + st*2304;
        const uint32_t* KlS = smu + 13824 + st*2304;
        const uint32_t* VhS = smu + 18432 + st*2304;
        const uint32_t* VlS = smu + 23040 + st*2304;

        float sf[8][4];
        #pragma unroll
        for (int nt = 0; nt < 8; nt++)
            #pragma unroll
            for (int i = 0; i < 4; i++) sf[nt][i] = 0.f;

        #pragma unroll
        for (int kc = 0; kc < 4; kc++) {
            uint32_t ah[4], al[4];
            const int k2a = qk + 8*kc, k2c = k2a + 4;
            const int r0o = (wr + qrow)*QP, r1o = (wr + qrow + 8)*QP;
            ah[0] = QhS[r0o + k2a]; ah[1] = QhS[r1o + k2a];
            ah[2] = QhS[r0o + k2c]; ah[3] = QhS[r1o + k2c];
            al[0] = QlS[r0o + k2a]; al[1] = QlS[r1o + k2a];
            al[2] = QlS[r0o + k2c]; al[3] = QlS[r1o + k2c];
            #pragma unroll
            for (int nt = 0; nt < 8; nt++) {
                const int co = (nt*8 + qrow)*QP;
                uint32_t bb[2] = { KhS[co + k2a], KhS[co + k2c] };
                MMA_BF16(sf[nt], ah, bb);
            }
            #pragma unroll
            for (int nt = 0; nt < 8; nt++) {
                const int co = (nt*8 + qrow)*QP;
                uint32_t bb[2] = { KlS[co + k2a], KlS[co + k2c] };
                MMA_BF16(sf[nt], ah, bb);
            }
            #pragma unroll
            for (int nt = 0; nt < 8; nt++) {
                const int co = (nt*8 + qrow)*QP;
                uint32_t bb[2] = { KhS[co + k2a], KhS[co + k2c] };
                MMA_BF16(sf[nt], al, bb);
            }
        }

        if (kt >= 2*qi) {
            #pragma unroll
            for (int nt = 0; nt < 8; nt++) {
                #pragma unroll
                for (int i = 0; i < 4; i++) {
                    int col_g = kt*64 + nt*8 + 2*qk + (i & 1);
                    int row_g = qi*128 + wr + qrow + 8*(i >> 1);
                    if (col_g > row_g) sf[nt][i] = -1e30f;
                }
            }
        }

        #pragma unroll
        for (int nt = 0; nt < 8; nt++) {
            sf[nt][0] = ex2(sf[nt][0]);
            sf[nt][1] = ex2(sf[nt][1]);
            sf[nt][2] = ex2(sf[nt][2]);
            sf[nt][3] = ex2(sf[nt][3]);
            l0 += sf[nt][0] + sf[nt][1];
            l1 += sf[nt][2] + sf[nt][3];
        }

        #pragma unroll
        for (int kc = 0; kc < 4; kc++) {
            uint32_t pah[4], pal[4];
            float r0, r1;
            pah[0] = pack_hi(sf[2*kc][0],   sf[2*kc][1],   r0, r1); pal[0] = pack_lo(r0, r1);
            pah[1] = pack_hi(sf[2*kc][2],   sf[2*kc][3],   r0, r1); pal[1] = pack_lo(r0, r1);
            pah[2] = pack_hi(sf[2*kc+1][0], sf[2*kc+1][1], r0, r1); pal[2] = pack_lo(r0, r1);
            pah[3] = pack_hi(sf[2*kc+1][2], sf[2*kc+1][3], r0, r1); pal[3] = pack_lo(r0, r1);
            const int kpa = 8*kc + qk, kpc = kpa + 4;
            #pragma unroll
            for (int nt = 0; nt < 8; nt++) {
                const int col = nt*8 + qrow;
                uint32_t bb[2] = { VhS[kpa*VP + col], VhS[kpc*VP + col] };
                MMA_BF16(of[nt], pah, bb);
            }
            #pragma unroll
            for (int nt = 0; nt < 8; nt++) {
                const int col = nt*8 + qrow;
                uint32_t bb[2] = { VlS[kpa*VP + col], VlS[kpc*VP + col] };
                MMA_BF16(of[nt], pah, bb);
            }
            #pragma unroll
            for (int nt = 0; nt < 8; nt++) {
                const int col = nt*8 + qrow;
                uint32_t bb[2] = { VhS[kpa*VP + col], VhS[kpc*VP + col] };
                MMA_BF16(of[nt], pal, bb);
            }
        }

        __syncthreads();

        if (kt + 2 < nkt) {
            const int nk = kt + 2;
            uint32_t kh_d = sbase + (9216  + st*2304 + krow*QP + kk2b)*4;
            uint32_t kl_d = sbase + (13824 + st*2304 + krow*QP + kk2b)*4;
            uint32_t vh_d = sbase + (18432 + st*2304 + vkp*VP + vdb)*4;
            uint32_t vl_d = sbase + (23040 + st*2304 + vkp*VP + vdb)*4;
            const uint32_t* skh = kh_g + kgo + (size_t)nk*64*32;
            const uint32_t* skl = kl_g + kgo + (size_t)nk*64*32;
            const uint32_t* svh = vh_g + vgo + (size_t)nk*32*64;
            const uint32_t* svl = vl_g + vgo + (size_t)nk*32*64;
            CPA16(kh_d, skh);  CPA16(kh_d+16, skh+4);
            CPA16(kl_d, skl);  CPA16(kl_d+16, skl+4);
            CPA16(vh_d, svh);  CPA16(vh_d+16, svh+4);
            CPA16(vl_d, svl);  CPA16(vl_d+16, svl+4);
            CPA_COMMIT();
        }
    }

    l0 += __shfl_xor_sync(0xffffffffu, l0, 1);
    l0 += __shfl_xor_sync(0xffffffffu, l0, 2);
    l1 += __shfl_xor_sync(0xffffffffu, l1, 1);
    l1 += __shfl_xor_sync(0xffffffffu, l1, 2);

    float inv0 = 1.f / l0, inv1 = 1.f / l1;
    #pragma unroll
    for (int nt = 0; nt < 8; nt++) {
        const int k2g = h*32 + nt*4 + qk;
        const int chn = k2g >> 3, wix = k2g & 7;
        const int row0 = b*SS + qi*128 + wr + qrow;
        float r0, r1;
        uint32_t hv = pack_hi(of[nt][0]*inv0, of[nt][1]*inv0, r0, r1);
        size_t di = ((size_t)chn*MROWS + row0)*8 + wix;
        cth[di] = hv;
        ctl[di] = pack_lo(r0, r1);
        hv = pack_hi(of[nt][2]*inv1, of[nt][3]*inv1, r0, r1);
        di = ((size_t)chn*MROWS + row0 + 8)*8 + wix;
        cth[di] = hv;
        ctl[di] = pack_lo(r0, r1);
    }
}

// ---------------------------------------------------------------------------
extern "C" void kernel_launch(void* const* d_in, const int* in_sizes, int n_in,
                              void* d_out, int out_size)
{
    (void)in_sizes; (void)n_in; (void)out_size;
    const float* query = (const float*)d_in[0];
    const float* key   = (const float*)d_in[1];
    const float* value = (const float*)d_in[2];
    const float* Wq = (const float*)d_in[4];
    const float* bq = (const float*)d_in[5];
    const float* Wk = (const float*)d_in[6];
    const float* bk = (const float*)d_in[7];
    const float* Wv = (const float*)d_in[8];
    const float* bv = (const float*)d_in[9];
    const float* Wo = (const float*)d_in[10];
    const float* bo = (const float*)d_in[11];
    float* out = (float*)d_out;

    float *qlin, *klin, *vlin, *cosT, *sinT;
    uint32_t *qh, *ql, *kh, *kl, *vh, *vl;
    uint32_t *ah, *al, *wh, *wl, *cth, *ctl;
    cudaGetSymbolAddress((void**)&qlin, g_qlin);
    cudaGetSymbolAddress((void**)&klin, g_klin);
    cudaGetSymbolAddress((void**)&vlin, g_vlin);
    cudaGetSymbolAddress((void**)&cosT, g_cos);
    cudaGetSymbolAddress((void**)&sinT, g_sin);
    cudaGetSymbolAddress((void**)&qh, g_qh);
    cudaGetSymbolAddress((void**)&ql, g_ql);
    cudaGetSymbolAddress((void**)&kh, g_kh);
    cudaGetSymbolAddress((void**)&kl, g_kl);
    cudaGetSymbolAddress((void**)&vh, g_vh);
    cudaGetSymbolAddress((void**)&vl, g_vl);
    cudaGetSymbolAddress((void**)&ah, g_ah);
    cudaGetSymbolAddress((void**)&al, g_al);
    cudaGetSymbolAddress((void**)&wh, g_wh);
    cudaGetSymbolAddress((void**)&wl, g_wl);
    cudaGetSymbolAddress((void**)&cth, g_cth);
    cudaGetSymbolAddress((void**)&ctl, g_ctl);

    const size_t ASTRIDE = (size_t)MROWS*512;
    const size_t WSTRIDE = (size_t)DD*512;

    cudaFuncSetAttribute(flash_tc5, cudaFuncAttributeMaxDynamicSharedMemorySize, FLASH_SMEM);
    cudaFuncSetAttribute(gemm_tc4,  cudaFuncAttributeMaxDynamicSharedMemorySize, GEMM_SMEM);

    rope_tables<<<SS*32/256, 256>>>(cosT, sinT);

    const int ABLK = MROWS*DD/8/256;   // 2048
    const int WBLK = DD*DD/8/256;      // 512
    dim3 sp3Grid(ABLK, 3);
    split_pack3<<<sp3Grid, 256>>>(query, key, value, ah, al, ASTRIDE);
    dim3 sp4Grid(WBLK, 4);
    split_pack4<<<sp4Grid, 256>>>(Wq, Wk, Wv, Wo, wh, wl, WSTRIDE);

    GArg gq = { ah + 0*ASTRIDE, al + 0*ASTRIDE, wh + 0*WSTRIDE, wl + 0*WSTRIDE, bq, qlin };
    GArg gk = { ah + 1*ASTRIDE, al + 1*ASTRIDE, wh + 1*WSTRIDE, wl + 1*WSTRIDE, bk, klin };
    GArg gv = { ah + 2*ASTRIDE, al + 2*ASTRIDE, wh + 2*WSTRIDE, wl + 2*WSTRIDE, bv, vlin };
    dim3 gemmGrid(DD/128, MROWS/128, 3);
    gemm_tc4<<<gemmGrid, 256, GEMM_SMEM>>>(gq, gk, gv);

    dim3 rsGrid((BB*HH*SS*16)/256, 2);
    rope_split<<<rsGrid, 256>>>(qlin, klin, cosT, sinT, qh, ql, kh, kl);
    v_split<<<(BB*HH*1024*16)/256, 256>>>(vlin, vh, vl);

    dim3 faGrid(SS/128, BB*HH);            // (16, 32)
    flash_tc5<<<faGrid, 256, FLASH_SMEM>>>(qh, ql, kh, kl, vh, vl, cth, ctl);

    GArg go = { cth, ctl, wh + 3*WSTRIDE, wl + 3*WSTRIDE, bo, out };
    dim3 gemmGridO(DD/128, MROWS/128, 1);
    gemm_tc4<<<gemmGridO, 256, GEMM_SMEM>>>(go, go, go);
}

// round 14
// speedup vs baseline: 1.1798x; 1.1798x over previous
#include <cuda_runtime.h>
#include <cuda_bf16.h>
#include <cuda_fp16.h>
#include <math.h>
#include <stdint.h>

#define BB 2
#define SS 2048
#define DD 1024
#define HH 16
#define DK 64
#define MROWS (BB*SS)   // 4096

// Scratch (device globals — allocation is forbidden)
__device__ float g_qlin[MROWS*DD];
__device__ float g_klin[MROWS*DD];
__device__ float g_vlin[MROWS*DD];
__device__ float g_cos[SS*32];
__device__ float g_sin[SS*32];
// bf16-split packed operands for flash: u32 = packed bf16x2
__device__ uint32_t g_qh[BB*HH*SS*32];
__device__ uint32_t g_ql[BB*HH*SS*32];
__device__ uint32_t g_kh[BB*HH*SS*32];
__device__ uint32_t g_kl[BB*HH*SS*32];
__device__ uint32_t g_vh[BB*HH*(SS/2)*DK];
__device__ uint32_t g_vl[BB*HH*(SS/2)*DK];
// fp16-split GEMM operands, CHUNK-MAJOR blocked: [chunk64][rows][8 u32]
__device__ uint32_t g_ah[3][MROWS*512];   // activation fp16 hi
__device__ uint32_t g_al[3][MROWS*512];   // activation fp16 lo
__device__ uint32_t g_wh[4][DD*512];      // weight fp16 hi (lo dropped: 2-pass)
__device__ uint32_t g_cth[MROWS*512];     // ctx fp16 hi
__device__ uint32_t g_ctl[MROWS*512];     // ctx fp16 lo

// ---------------------------------------------------------------------------
// bf16 split helpers (flash path)
__device__ __forceinline__ uint32_t pack_hi(float a, float b, float& ra, float& rb)
{
    __nv_bfloat16 ha = __float2bfloat16(a);
    __nv_bfloat16 hb = __float2bfloat16(b);
    ra = a - __bfloat162float(ha);
    rb = b - __bfloat162float(hb);
    __nv_bfloat162 p;
    p.x = ha; p.y = hb;
    return *reinterpret_cast<uint32_t*>(&p);
}
__device__ __forceinline__ uint32_t pack_lo(float ra, float rb)
{
    __nv_bfloat162 p = __floats2bfloat162_rn(ra, rb);
    return *reinterpret_cast<uint32_t*>(&p);
}
// fp16 split helpers (GEMM path)
__device__ __forceinline__ uint32_t pack_hi16(float a, float b, float& ra, float& rb)
{
    __half ha = __float2half_rn(a);
    __half hb = __float2half_rn(b);
    ra = a - __half2float(ha);
    rb = b - __half2float(hb);
    __half2 p; p.x = ha; p.y = hb;
    return *reinterpret_cast<uint32_t*>(&p);
}
__device__ __forceinline__ uint32_t pack_lo16(float ra, float rb)
{
    __half2 p = __floats2half2_rn(ra, rb);
    return *reinterpret_cast<uint32_t*>(&p);
}
__device__ __forceinline__ float ex2(float x)
{
    float r;
    asm("ex2.approx.f32 %0, %1;" : "=f"(r) : "f"(x));
    return r;
}

#define MMA_BF16(d, a, b) \
    asm volatile("mma.sync.aligned.m16n8k16.row.col.f32.bf16.bf16.f32 " \
        "{%0,%1,%2,%3}, {%4,%5,%6,%7}, {%8,%9}, {%0,%1,%2,%3};" \
        : "+f"(d[0]), "+f"(d[1]), "+f"(d[2]), "+f"(d[3]) \
        : "r"(a[0]), "r"(a[1]), "r"(a[2]), "r"(a[3]), "r"(b[0]), "r"(b[1]))

#define MMA_F16(d, a, b) \
    asm volatile("mma.sync.aligned.m16n8k16.row.col.f32.f16.f16.f32 " \
        "{%0,%1,%2,%3}, {%4,%5,%6,%7}, {%8,%9}, {%0,%1,%2,%3};" \
        : "+f"(d[0]), "+f"(d[1]), "+f"(d[2]), "+f"(d[3]) \
        : "r"(a[0]), "r"(a[1]), "r"(a[2]), "r"(a[3]), "r"(b[0]), "r"(b[1]))

#define CPA16(dst, src)  asm volatile("cp.async.cg.shared.global [%0], [%1], 16;" :: "r"(dst), "l"(src))
#define CPA_COMMIT()     asm volatile("cp.async.commit_group;" ::: "memory")
#define CPA_WAIT(N)      asm volatile("cp.async.wait_group %0;" :: "n"(N) : "memory")

// ---------------------------------------------------------------------------
__global__ __launch_bounds__(256) void rope_tables(float* cosT, float* sinT)
{
    const int t = blockIdx.x * 256 + threadIdx.x;
    const int j = t & 31;
    const int s = t >> 5;
    double inv = exp(-(double)j * 0.28782313662425575);
    double sd, cd;
    sincos((double)s * inv, &sd, &cd);
    cosT[t] = (float)cd;
    sinT[t] = (float)sd;
}

// ---------------------------------------------------------------------------
// Activations: fp16 hi+lo, chunk-major blocked.
// ---------------------------------------------------------------------------
__global__ __launch_bounds__(256) void split_act3(
    const float* __restrict__ X0, const float* __restrict__ X1,
    const float* __restrict__ X2,
    uint32_t* __restrict__ Xh, uint32_t* __restrict__ Xl, size_t ostride)
{
    const float* X = (blockIdx.y == 0) ? X0 : ((blockIdx.y == 1) ? X1 : X2);
    uint32_t* H = Xh + blockIdx.y * ostride;
    uint32_t* L = Xl + blockIdx.y * ostride;
    const size_t t = (size_t)blockIdx.x * 256 + threadIdx.x;
    const int row   = (int)(t >> 7);
    const int rem   = (int)(t & 127);
    const int chunk = rem >> 1;
    const int half  = rem & 1;
    float4 v0 = ((const float4*)X)[2*t];
    float4 v1 = ((const float4*)X)[2*t+1];
    float r0, r1, r2, r3, r4, r5, r6, r7;
    uint4 h, l;
    h.x = pack_hi16(v0.x, v0.y, r0, r1);
    h.y = pack_hi16(v0.z, v0.w, r2, r3);
    h.z = pack_hi16(v1.x, v1.y, r4, r5);
    h.w = pack_hi16(v1.z, v1.w, r6, r7);
    l.x = pack_lo16(r0, r1); l.y = pack_lo16(r2, r3);
    l.z = pack_lo16(r4, r5); l.w = pack_lo16(r6, r7);
    const size_t d = ((size_t)chunk * MROWS + row) * 2 + half;
    ((uint4*)H)[d] = h;
    ((uint4*)L)[d] = l;
}

// Weights: fp16 hi only, chunk-major blocked.
__global__ __launch_bounds__(256) void split_w4(
    const float* __restrict__ X0, const float* __restrict__ X1,
    const float* __restrict__ X2, const float* __restrict__ X3,
    uint32_t* __restrict__ Xh, size_t ostride)
{
    const float* X = (blockIdx.y == 0) ? X0 : ((blockIdx.y == 1) ? X1 :
                     ((blockIdx.y == 2) ? X2 : X3));
    uint32_t* H = Xh + blockIdx.y * ostride;
    const size_t t = (size_t)blockIdx.x * 256 + threadIdx.x;
    const int row   = (int)(t >> 7);
    const int rem   = (int)(t & 127);
    const int chunk = rem >> 1;
    const int half  = rem & 1;
    float4 v0 = ((const float4*)X)[2*t];
    float4 v1 = ((const float4*)X)[2*t+1];
    uint4 h;
    __half2 p;
    p = __floats2half2_rn(v0.x, v0.y); h.x = *(uint32_t*)&p;
    p = __floats2half2_rn(v0.z, v0.w); h.y = *(uint32_t*)&p;
    p = __floats2half2_rn(v1.x, v1.y); h.z = *(uint32_t*)&p;
    p = __floats2half2_rn(v1.z, v1.w); h.w = *(uint32_t*)&p;
    const size_t d = ((size_t)chunk * DD + row) * 2 + half;
    ((uint4*)H)[d] = h;
}

// ---------------------------------------------------------------------------
// gemm_fp16: 2-pass exact-activation fp16 GEMM. D = (Ah + Al) * Wh^T + bias.
// Error = A*Wl (dropped) ~7e-5 relative. 128x128 tile, 8 warps, BK=16,
// double-buffered LDG+STS path (R12 winner), chunk-major blocked operands.
// 3 smem arrays (Ah, Al, Wh), 32 MMAs/iter/warp (was 48).
// ---------------------------------------------------------------------------
#define GP 136
#define ACH 32768   // u32 per chunk, activation arrays
#define WCH 8192    // u32 per chunk, weight arrays

struct GArg {
    const uint32_t *ah, *al, *wh;
    const float* bias;
    float* c;
};

__global__ __launch_bounds__(256, 2) void gemm_fp16(GArg g0, GArg g1, GArg g2)
{
    GArg g = (blockIdx.z == 0) ? g0 : ((blockIdx.z == 1) ? g1 : g2);
    __shared__ uint32_t Ah[2][8][GP], Al[2][8][GP], Wh[2][8][GP];

    const int tid = threadIdx.x;
    const int bm = blockIdx.y, bn = blockIdx.x;
    const int lane = tid & 31, wid = tid >> 5;
    const int wm = (wid >> 2) * 64;
    const int wn = (wid & 3) * 32;
    const int qrow = lane >> 2, qk = lane & 3;

    const int r = tid >> 1;
    const int k2b = (tid & 1) * 4;

    const uint32_t* AhG = g.ah + ((size_t)(bm*128 + r))*8 + k2b;
    const uint32_t* AlG = g.al + ((size_t)(bm*128 + r))*8 + k2b;
    const uint32_t* WhG = g.wh + ((size_t)(bn*128 + r))*8 + k2b;

    float d[4][4][4];
    #pragma unroll
    for (int mt = 0; mt < 4; mt++)
        #pragma unroll
        for (int nt = 0; nt < 4; nt++)
            #pragma unroll
            for (int i = 0; i < 4; i++) d[mt][nt][i] = 0.f;

    {
        uint4 a = *(const uint4*)AhG;
        uint4 b = *(const uint4*)AlG;
        uint4 c = *(const uint4*)WhG;
        Ah[0][k2b+0][r] = a.x; Ah[0][k2b+1][r] = a.y; Ah[0][k2b+2][r] = a.z; Ah[0][k2b+3][r] = a.w;
        Al[0][k2b+0][r] = b.x; Al[0][k2b+1][r] = b.y; Al[0][k2b+2][r] = b.z; Al[0][k2b+3][r] = b.w;
        Wh[0][k2b+0][r] = c.x; Wh[0][k2b+1][r] = c.y; Wh[0][k2b+2][r] = c.z; Wh[0][k2b+3][r] = c.w;
    }
    __syncthreads();

    int st = 0;
    for (int c = 1; c <= 64; c++) {
        uint4 na, nb, nc;
        const bool has = (c < 64);
        if (has) {
            na = *(const uint4*)(AhG + (size_t)c*ACH);
            nb = *(const uint4*)(AlG + (size_t)c*ACH);
            nc = *(const uint4*)(WhG + (size_t)c*WCH);
        }

        uint32_t afh[4][4], afl[4][4], bfh[4][2];
        #pragma unroll
        for (int mt = 0; mt < 4; mt++) {
            int m0 = wm + mt*16 + qrow;
            #pragma unroll
            for (int i = 0; i < 4; i++) {
                int m  = m0 + ((i & 1) << 3);
                int k2 = qk + ((i >> 1) << 2);
                afh[mt][i] = Ah[st][k2][m];
                afl[mt][i] = Al[st][k2][m];
            }
        }
        #pragma unroll
        for (int nt = 0; nt < 4; nt++) {
            int n0 = wn + nt*8 + qrow;
            #pragma unroll
            for (int i = 0; i < 2; i++)
                bfh[nt][i] = Wh[st][qk + 4*i][n0];
        }

        #pragma unroll
        for (int mt = 0; mt < 4; mt++)
            #pragma unroll
            for (int nt = 0; nt < 4; nt++) {
                MMA_F16(d[mt][nt], afh[mt], bfh[nt]);
                MMA_F16(d[mt][nt], afl[mt], bfh[nt]);
            }

        if (has) {
            int s2 = st ^ 1;
            Ah[s2][k2b+0][r] = na.x; Ah[s2][k2b+1][r] = na.y; Ah[s2][k2b+2][r] = na.z; Ah[s2][k2b+3][r] = na.w;
            Al[s2][k2b+0][r] = nb.x; Al[s2][k2b+1][r] = nb.y; Al[s2][k2b+2][r] = nb.z; Al[s2][k2b+3][r] = nb.w;
            Wh[s2][k2b+0][r] = nc.x; Wh[s2][k2b+1][r] = nc.y; Wh[s2][k2b+2][r] = nc.z; Wh[s2][k2b+3][r] = nc.w;
        }
        __syncthreads();
        st ^= 1;
    }

    #pragma unroll
    for (int mt = 0; mt < 4; mt++)
        #pragma unroll
        for (int nt = 0; nt < 4; nt++) {
            int col0 = bn*128 + wn + nt*8 + 2*qk;
            float b0 = g.bias[col0], b1 = g.bias[col0+1];
            #pragma unroll
            for (int half = 0; half < 2; half++) {
                int row = bm*128 + wm + mt*16 + qrow + 8*half;
                float2 v;
                v.x = d[mt][nt][2*half+0] + b0;
                v.y = d[mt][nt][2*half+1] + b1;
                *(float2*)&g.c[(size_t)row*DD + col0] = v;
            }
        }
}

// ---------------------------------------------------------------------------
// RoPE + head-transpose + bf16 split for Q,K (flash path). Q scale folds log2e.
// ---------------------------------------------------------------------------
__global__ __launch_bounds__(256) void rope_split(
    const float* __restrict__ qlin, const float* __restrict__ klin,
    const float* __restrict__ cosT, const float* __restrict__ sinT,
    uint32_t* __restrict__ qh, uint32_t* __restrict__ ql,
    uint32_t* __restrict__ kh, uint32_t* __restrict__ kl)
{
    const int t = blockIdx.x * 256 + threadIdx.x;
    const float* src = blockIdx.y ? klin : qlin;
    uint32_t* dh = blockIdx.y ? kh : qh;
    uint32_t* dl = blockIdx.y ? kl : ql;
    const float scale = blockIdx.y ? 1.0f : 0.18033688011112042f;  // 0.125*log2(e)

    const int k2 = t & 15;
    const int s  = (t >> 4) & (SS - 1);
    const int bh = t >> 15;
    const int b = bh >> 4, h = bh & 15;
    const int j0 = 2*k2, j1 = 2*k2 + 1;

    const float* sp = src + ((size_t)(b*SS + s))*DD + h*DK;
    float x0 = sp[j0],      x1 = sp[j1];
    float y0 = sp[j0 + 32], y1 = sp[j1 + 32];
    float c0 = cosT[s*32 + j0], c1 = cosT[s*32 + j1];
    float s0 = sinT[s*32 + j0], s1 = sinT[s*32 + j1];

    float o0 = (x0*c0 - y0*s0) * scale;
    float o1 = (x1*c1 - y1*s1) * scale;
    float p0 = (y0*c0 + x0*s0) * scale;
    float p1 = (y1*c1 + x1*s1) * scale;

    size_t base = ((size_t)bh*SS + s)*32;
    float r0, r1;
    uint32_t hv = pack_hi(o0, o1, r0, r1);
    dh[base + k2] = hv;            dl[base + k2] = pack_lo(r0, r1);
    hv = pack_hi(p0, p1, r0, r1);
    dh[base + k2 + 16] = hv;       dl[base + k2 + 16] = pack_lo(r0, r1);
}

// ---------------------------------------------------------------------------
__global__ __launch_bounds__(256) void v_split(
    const float* __restrict__ vlin,
    uint32_t* __restrict__ vh, uint32_t* __restrict__ vl)
{
    const int t = blockIdx.x * 256 + threadIdx.x;
    const int d4 = (t & 15) * 4;
    const int kp = (t >> 4) & 1023;
    const int bh = t >> 14;
    const int b = bh >> 4, h = bh & 15;

    const float* r0p = vlin + ((size_t)(b*SS + 2*kp))*DD + h*DK + d4;
    float4 a = *(const float4*)r0p;
    float4 c = *(const float4*)(r0p + DD);

    uint32_t hh[4], ll[4];
    float ra, rb;
    hh[0] = pack_hi(a.x, c.x, ra, rb); ll[0] = pack_lo(ra, rb);
    hh[1] = pack_hi(a.y, c.y, ra, rb); ll[1] = pack_lo(ra, rb);
    hh[2] = pack_hi(a.z, c.z, ra, rb); ll[2] = pack_lo(ra, rb);
    hh[3] = pack_hi(a.w, c.w, ra, rb); ll[3] = pack_lo(ra, rb);

    size_t base = ((size_t)bh*1024 + kp)*64 + d4;
    *(uint4*)&vh[base] = make_uint4(hh[0], hh[1], hh[2], hh[3]);
    *(uint4*)&vl[base] = make_uint4(ll[0], ll[1], ll[2], ll[3]);
}

// ---------------------------------------------------------------------------
// Flash v5: no-max softmax, cp.async double-buffered K/V, 3-pass bf16 MMAs.
// Epilogue writes fp16 hi/lo ctx in chunk-major blocked layout (Wo is fp16).
// ---------------------------------------------------------------------------
#define QP 36
#define VP 72
#define FLASH_SMEM (27648*4)

__global__ __launch_bounds__(256, 2) void flash_tc5(
    const uint32_t* __restrict__ qh_g, const uint32_t* __restrict__ ql_g,
    const uint32_t* __restrict__ kh_g, const uint32_t* __restrict__ kl_g,
    const uint32_t* __restrict__ vh_g, const uint32_t* __restrict__ vl_g,
    uint32_t* __restrict__ cth, uint32_t* __restrict__ ctl)
{
    extern __shared__ uint32_t smu[];
    const uint32_t sbase = (uint32_t)__cvta_generic_to_shared(smu);

    const int tid = threadIdx.x;
    const int qi = 15 - blockIdx.x;
    const int bh = blockIdx.y;
    const int b = bh >> 4, h = bh & 15;
    const int lane = tid & 31, wid = tid >> 5;
    const int qk = lane & 3, qrow = lane >> 2;
    const int wr = wid * 16;
    const int nkt = 2*qi + 2;

    const int krow = tid >> 2, kk2b = (tid & 3) * 8;
    const int vkp  = tid >> 3, vdb  = (tid & 7) * 8;
    const size_t kgo = ((size_t)bh*SS + krow)*32 + kk2b;
    const size_t vgo = ((size_t)bh*1024 + vkp)*64 + vdb;

    {
        const int row = tid >> 1, cb = (tid & 1) * 16;
        const uint32_t* sh = qh_g + ((size_t)bh*SS + qi*128 + row)*32 + cb;
        const uint32_t* sl = ql_g + ((size_t)bh*SS + qi*128 + row)*32 + cb;
        uint32_t dh = sbase + (row*QP + cb)*4;
        uint32_t dl = sbase + (4608 + row*QP + cb)*4;
        CPA16(dh,    sh);     CPA16(dh+16, sh+4);
        CPA16(dh+32, sh+8);   CPA16(dh+48, sh+12);
        CPA16(dl,    sl);     CPA16(dl+16, sl+4);
        CPA16(dl+32, sl+8);   CPA16(dl+48, sl+12);
    }
    CPA_COMMIT();

    #pragma unroll
    for (int pk = 0; pk < 2; pk++) {
        uint32_t kh_d = sbase + (9216  + pk*2304 + krow*QP + kk2b)*4;
        uint32_t kl_d = sbase + (13824 + pk*2304 + krow*QP + kk2b)*4;
        uint32_t vh_d = sbase + (18432 + pk*2304 + vkp*VP + vdb)*4;
        uint32_t vl_d = sbase + (23040 + pk*2304 + vkp*VP + vdb)*4;
        const uint32_t* skh = kh_g + kgo + (size_t)pk*64*32;
        const uint32_t* skl = kl_g + kgo + (size_t)pk*64*32;
        const uint32_t* svh = vh_g + vgo + (size_t)pk*32*64;
        const uint32_t* svl = vl_g + vgo + (size_t)pk*32*64;
        CPA16(kh_d, skh);  CPA16(kh_d+16, skh+4);
        CPA16(kl_d, skl);  CPA16(kl_d+16, skl+4);
        CPA16(vh_d, svh);  CPA16(vh_d+16, svh+4);
        CPA16(vl_d, svl);  CPA16(vl_d+16, svl+4);
        CPA_COMMIT();
    }

    float l0 = 0.f, l1 = 0.f;
    float of[8][4];
    #pragma unroll
    for (int nt = 0; nt < 8; nt++)
        #pragma unroll
        for (int i = 0; i < 4; i++) of[nt][i] = 0.f;

    const uint32_t* QhS = smu;
    const uint32_t* QlS = smu + 4608;

    for (int kt = 0; kt < nkt; kt++) {
        const int st = kt & 1;
        if (kt + 1 < nkt) { CPA_WAIT(1); } else { CPA_WAIT(0); }
        __syncthreads();

        const uint32_t* KhS = smu + 9216  + st*2304;
        const uint32_t* KlS = smu + 13824 + st*2304;
        const uint32_t* VhS = smu + 18432 + st*2304;
        const uint32_t* VlS = smu + 23040 + st*2304;

        float sf[8][4];
        #pragma unroll
        for (int nt = 0; nt < 8; nt++)
            #pragma unroll
            for (int i = 0; i < 4; i++) sf[nt][i] = 0.f;

        #pragma unroll
        for (int kc = 0; kc < 4; kc++) {
            uint32_t ah[4], al[4];
            const int k2a = qk + 8*kc, k2c = k2a + 4;
            const int r0o = (wr + qrow)*QP, r1o = (wr + qrow + 8)*QP;
            ah[0] = QhS[r0o + k2a]; ah[1] = QhS[r1o + k2a];
            ah[2] = QhS[r0o + k2c]; ah[3] = QhS[r1o + k2c];
            al[0] = QlS[r0o + k2a]; al[1] = QlS[r1o + k2a];
            al[2] = QlS[r0o + k2c]; al[3] = QlS[r1o + k2c];
            #pragma unroll
            for (int nt = 0; nt < 8; nt++) {
                const int co = (nt*8 + qrow)*QP;
                uint32_t bb[2] = { KhS[co + k2a], KhS[co + k2c] };
                MMA_BF16(sf[nt], ah, bb);
            }
            #pragma unroll
            for (int nt = 0; nt < 8; nt++) {
                const int co = (nt*8 + qrow)*QP;
                uint32_t bb[2] = { KlS[co + k2a], KlS[co + k2c] };
                MMA_BF16(sf[nt], ah, bb);
            }
            #pragma unroll
            for (int nt = 0; nt < 8; nt++) {
                const int co = (nt*8 + qrow)*QP;
                uint32_t bb[2] = { KhS[co + k2a], KhS[co + k2c] };
                MMA_BF16(sf[nt], al, bb);
            }
        }

        if (kt >= 2*qi) {
            #pragma unroll
            for (int nt = 0; nt < 8; nt++) {
                #pragma unroll
                for (int i = 0; i < 4; i++) {
                    int col_g = kt*64 + nt*8 + 2*qk + (i & 1);
                    int row_g = qi*128 + wr + qrow + 8*(i >> 1);
                    if (col_g > row_g) sf[nt][i] = -1e30f;
                }
            }
        }

        #pragma unroll
        for (int nt = 0; nt < 8; nt++) {
            sf[nt][0] = ex2(sf[nt][0]);
            sf[nt][1] = ex2(sf[nt][1]);
            sf[nt][2] = ex2(sf[nt][2]);
            sf[nt][3] = ex2(sf[nt][3]);
            l0 += sf[nt][0] + sf[nt][1];
            l1 += sf[nt][2] + sf[nt][3];
        }

        #pragma unroll
        for (int kc = 0; kc < 4; kc++) {
            uint32_t pah[4], pal[4];
            float r0, r1;
            pah[0] = pack_hi(sf[2*kc][0],   sf[2*kc][1],   r0, r1); pal[0] = pack_lo(r0, r1);
            pah[1] = pack_hi(sf[2*kc][2],   sf[2*kc][3],   r0, r1); pal[1] = pack_lo(r0, r1);
            pah[2] = pack_hi(sf[2*kc+1][0], sf[2*kc+1][1], r0, r1); pal[2] = pack_lo(r0, r1);
            pah[3] = pack_hi(sf[2*kc+1][2], sf[2*kc+1][3], r0, r1); pal[3] = pack_lo(r0, r1);
            const int kpa = 8*kc + qk, kpc = kpa + 4;
            #pragma unroll
            for (int nt = 0; nt < 8; nt++) {
                const int col = nt*8 + qrow;
                uint32_t bb[2] = { VhS[kpa*VP + col], VhS[kpc*VP + col] };
                MMA_BF16(of[nt], pah, bb);
            }
            #pragma unroll
            for (int nt = 0; nt < 8; nt++) {
                const int col = nt*8 + qrow;
                uint32_t bb[2] = { VlS[kpa*VP + col], VlS[kpc*VP + col] };
                MMA_BF16(of[nt], pah, bb);
            }
            #pragma unroll
            for (int nt = 0; nt < 8; nt++) {
                const int col = nt*8 + qrow;
                uint32_t bb[2] = { VhS[kpa*VP + col], VhS[kpc*VP + col] };
                MMA_BF16(of[nt], pal, bb);
            }
        }

        __syncthreads();

        if (kt + 2 < nkt) {
            const int nk = kt + 2;
            uint32_t kh_d = sbase + (9216  + st*2304 + krow*QP + kk2b)*4;
            uint32_t kl_d = sbase + (13824 + st*2304 + krow*QP + kk2b)*4;
            uint32_t vh_d = sbase + (18432 + st*2304 + vkp*VP + vdb)*4;
            uint32_t vl_d = sbase + (23040 + st*2304 + vkp*VP + vdb)*4;
            const uint32_t* skh = kh_g + kgo + (size_t)nk*64*32;
            const uint32_t* skl = kl_g + kgo + (size_t)nk*64*32;
            const uint32_t* svh = vh_g + vgo + (size_t)nk*32*64;
            const uint32_t* svl = vl_g + vgo + (size_t)nk*32*64;
            CPA16(kh_d, skh);  CPA16(kh_d+16, skh+4);
            CPA16(kl_d, skl);  CPA16(kl_d+16, skl+4);
            CPA16(vh_d, svh);  CPA16(vh_d+16, svh+4);
            CPA16(vl_d, svl);  CPA16(vl_d+16, svl+4);
            CPA_COMMIT();
        }
    }

    l0 += __shfl_xor_sync(0xffffffffu, l0, 1);
    l0 += __shfl_xor_sync(0xffffffffu, l0, 2);
    l1 += __shfl_xor_sync(0xffffffffu, l1, 1);
    l1 += __shfl_xor_sync(0xffffffffu, l1, 2);

    float inv0 = 1.f / l0, inv1 = 1.f / l1;
    #pragma unroll
    for (int nt = 0; nt < 8; nt++) {
        const int k2g = h*32 + nt*4 + qk;
        const int chn = k2g >> 3, wix = k2g & 7;
        const int row0 = b*SS + qi*128 + wr + qrow;
        float r0, r1;
        uint32_t hv = pack_hi16(of[nt][0]*inv0, of[nt][1]*inv0, r0, r1);
        size_t di = ((size_t)chn*MROWS + row0)*8 + wix;
        cth[di] = hv;
        ctl[di] = pack_lo16(r0, r1);
        hv = pack_hi16(of[nt][2]*inv1, of[nt][3]*inv1, r0, r1);
        di = ((size_t)chn*MROWS + row0 + 8)*8 + wix;
        cth[di] = hv;
        ctl[di] = pack_lo16(r0, r1);
    }
}

// ---------------------------------------------------------------------------
extern "C" void kernel_launch(void* const* d_in, const int* in_sizes, int n_in,
                              void* d_out, int out_size)
{
    (void)in_sizes; (void)n_in; (void)out_size;
    const float* query = (const float*)d_in[0];
    const float* key   = (const float*)d_in[1];
    const float* value = (const float*)d_in[2];
    const float* Wq = (const float*)d_in[4];
    const float* bq = (const float*)d_in[5];
    const float* Wk = (const float*)d_in[6];
    const float* bk = (const float*)d_in[7];
    const float* Wv = (const float*)d_in[8];
    const float* bv = (const float*)d_in[9];
    const float* Wo = (const float*)d_in[10];
    const float* bo = (const float*)d_in[11];
    float* out = (float*)d_out;

    float *qlin, *klin, *vlin, *cosT, *sinT;
    uint32_t *qh, *ql, *kh, *kl, *vh, *vl;
    uint32_t *ah, *al, *wh, *cth, *ctl;
    cudaGetSymbolAddress((void**)&qlin, g_qlin);
    cudaGetSymbolAddress((void**)&klin, g_klin);
    cudaGetSymbolAddress((void**)&vlin, g_vlin);
    cudaGetSymbolAddress((void**)&cosT, g_cos);
    cudaGetSymbolAddress((void**)&sinT, g_sin);
    cudaGetSymbolAddress((void**)&qh, g_qh);
    cudaGetSymbolAddress((void**)&ql, g_ql);
    cudaGetSymbolAddress((void**)&kh, g_kh);
    cudaGetSymbolAddress((void**)&kl, g_kl);
    cudaGetSymbolAddress((void**)&vh, g_vh);
    cudaGetSymbolAddress((void**)&vl, g_vl);
    cudaGetSymbolAddress((void**)&ah, g_ah);
    cudaGetSymbolAddress((void**)&al, g_al);
    cudaGetSymbolAddress((void**)&wh, g_wh);
    cudaGetSymbolAddress((void**)&cth, g_cth);
    cudaGetSymbolAddress((void**)&ctl, g_ctl);

    const size_t ASTRIDE = (size_t)MROWS*512;
    const size_t WSTRIDE = (size_t)DD*512;

    cudaFuncSetAttribute(flash_tc5, cudaFuncAttributeMaxDynamicSharedMemorySize, FLASH_SMEM);

    rope_tables<<<SS*32/256, 256>>>(cosT, sinT);

    const int ABLK = MROWS*DD/8/256;   // 2048
    const int WBLK = DD*DD/8/256;      // 512
    dim3 sp3Grid(ABLK, 3);
    split_act3<<<sp3Grid, 256>>>(query, key, value, ah, al, ASTRIDE);
    dim3 sp4Grid(WBLK, 4);
    split_w4<<<sp4Grid, 256>>>(Wq, Wk, Wv, Wo, wh, WSTRIDE);

    GArg gq = { ah + 0*ASTRIDE, al + 0*ASTRIDE, wh + 0*WSTRIDE, bq, qlin };
    GArg gk = { ah + 1*ASTRIDE, al + 1*ASTRIDE, wh + 1*WSTRIDE, bk, klin };
    GArg gv = { ah + 2*ASTRIDE, al + 2*ASTRIDE, wh + 2*WSTRIDE, bv, vlin };
    dim3 gemmGrid(DD/128, MROWS/128, 3);
    gemm_fp16<<<gemmGrid, 256>>>(gq, gk, gv);

    dim3 rsGrid((BB*HH*SS*16)/256, 2);
    rope_split<<<rsGrid, 256>>>(qlin, klin, cosT, sinT, qh, ql, kh, kl);
    v_split<<<(BB*HH*1024*16)/256, 256>>>(vlin, vh, vl);

    dim3 faGrid(SS/128, BB*HH);            // (16, 32)
    flash_tc5<<<faGrid, 256, FLASH_SMEM>>>(qh, ql, kh, kl, vh, vl, cth, ctl);

    GArg go = { cth, ctl, wh + 3*WSTRIDE, bo, out };
    dim3 gemmGridO(DD/128, MROWS/128, 1);
    gemm_fp16<<<gemmGridO, 256>>>(go, go, go);
}

// round 15
// speedup vs baseline: 1.3785x; 1.1685x over previous
#include <cuda_runtime.h>
#include <cuda_bf16.h>
#include <cuda_fp16.h>
#include <math.h>
#include <stdint.h>

#define BB 2
#define SS 2048
#define DD 1024
#define HH 16
#define DK 64
#define MROWS (BB*SS)   // 4096

// Scratch (device globals — allocation is forbidden)
__device__ float g_qlin[MROWS*DD];
__device__ float g_klin[MROWS*DD];
__device__ float g_vlin[MROWS*DD];
__device__ float g_cos[SS*32];
__device__ float g_sin[SS*32];
// fp16 packed operands for flash: u32 = packed half2
__device__ uint32_t g_qh[BB*HH*SS*32];    // Q fp16 hi
__device__ uint32_t g_ql[BB*HH*SS*32];    // Q fp16 lo (exact residual)
__device__ uint32_t g_kh[BB*HH*SS*32];    // K fp16 (single)
__device__ uint32_t g_vh[BB*HH*(SS/2)*DK];// V fp16 (single), key-pair packed
// fp16-split GEMM operands, CHUNK-MAJOR blocked: [chunk64][rows][8 u32]
__device__ uint32_t g_ah[3][MROWS*512];   // activation fp16 hi
__device__ uint32_t g_al[3][MROWS*512];   // activation fp16 lo
__device__ uint32_t g_wh[4][DD*512];      // weight fp16 (single)
__device__ uint32_t g_cth[MROWS*512];     // ctx fp16 hi
__device__ uint32_t g_ctl[MROWS*512];     // ctx fp16 lo

// ---------------------------------------------------------------------------
// fp16 split helpers
__device__ __forceinline__ uint32_t pack_hi16(float a, float b, float& ra, float& rb)
{
    __half ha = __float2half_rn(a);
    __half hb = __float2half_rn(b);
    ra = a - __half2float(ha);
    rb = b - __half2float(hb);
    __half2 p; p.x = ha; p.y = hb;
    return *reinterpret_cast<uint32_t*>(&p);
}
__device__ __forceinline__ uint32_t pack_lo16(float ra, float rb)
{
    __half2 p = __floats2half2_rn(ra, rb);
    return *reinterpret_cast<uint32_t*>(&p);
}
__device__ __forceinline__ uint32_t pack16(float a, float b)
{
    __half2 p = __floats2half2_rn(a, b);
    return *reinterpret_cast<uint32_t*>(&p);
}
__device__ __forceinline__ float ex2(float x)
{
    float r;
    asm("ex2.approx.f32 %0, %1;" : "=f"(r) : "f"(x));
    return r;
}

#define MMA_F16(d, a, b) \
    asm volatile("mma.sync.aligned.m16n8k16.row.col.f32.f16.f16.f32 " \
        "{%0,%1,%2,%3}, {%4,%5,%6,%7}, {%8,%9}, {%0,%1,%2,%3};" \
        : "+f"(d[0]), "+f"(d[1]), "+f"(d[2]), "+f"(d[3]) \
        : "r"(a[0]), "r"(a[1]), "r"(a[2]), "r"(a[3]), "r"(b[0]), "r"(b[1]))

#define CPA16(dst, src)  asm volatile("cp.async.cg.shared.global [%0], [%1], 16;" :: "r"(dst), "l"(src))
#define CPA_COMMIT()     asm volatile("cp.async.commit_group;" ::: "memory")
#define CPA_WAIT(N)      asm volatile("cp.async.wait_group %0;" :: "n"(N) : "memory")

// ---------------------------------------------------------------------------
__global__ __launch_bounds__(256) void rope_tables(float* cosT, float* sinT)
{
    const int t = blockIdx.x * 256 + threadIdx.x;
    const int j = t & 31;
    const int s = t >> 5;
    double inv = exp(-(double)j * 0.28782313662425575);
    double sd, cd;
    sincos((double)s * inv, &sd, &cd);
    cosT[t] = (float)cd;
    sinT[t] = (float)sd;
}

// ---------------------------------------------------------------------------
// Activations: fp16 hi+lo, chunk-major blocked.
// ---------------------------------------------------------------------------
__global__ __launch_bounds__(256) void split_act3(
    const float* __restrict__ X0, const float* __restrict__ X1,
    const float* __restrict__ X2,
    uint32_t* __restrict__ Xh, uint32_t* __restrict__ Xl, size_t ostride)
{
    const float* X = (blockIdx.y == 0) ? X0 : ((blockIdx.y == 1) ? X1 : X2);
    uint32_t* H = Xh + blockIdx.y * ostride;
    uint32_t* L = Xl + blockIdx.y * ostride;
    const size_t t = (size_t)blockIdx.x * 256 + threadIdx.x;
    const int row   = (int)(t >> 7);
    const int rem   = (int)(t & 127);
    const int chunk = rem >> 1;
    const int half  = rem & 1;
    float4 v0 = ((const float4*)X)[2*t];
    float4 v1 = ((const float4*)X)[2*t+1];
    float r0, r1, r2, r3, r4, r5, r6, r7;
    uint4 h, l;
    h.x = pack_hi16(v0.x, v0.y, r0, r1);
    h.y = pack_hi16(v0.z, v0.w, r2, r3);
    h.z = pack_hi16(v1.x, v1.y, r4, r5);
    h.w = pack_hi16(v1.z, v1.w, r6, r7);
    l.x = pack_lo16(r0, r1); l.y = pack_lo16(r2, r3);
    l.z = pack_lo16(r4, r5); l.w = pack_lo16(r6, r7);
    const size_t d = ((size_t)chunk * MROWS + row) * 2 + half;
    ((uint4*)H)[d] = h;
    ((uint4*)L)[d] = l;
}

// Weights: fp16 single, chunk-major blocked.
__global__ __launch_bounds__(256) void split_w4(
    const float* __restrict__ X0, const float* __restrict__ X1,
    const float* __restrict__ X2, const float* __restrict__ X3,
    uint32_t* __restrict__ Xh, size_t ostride)
{
    const float* X = (blockIdx.y == 0) ? X0 : ((blockIdx.y == 1) ? X1 :
                     ((blockIdx.y == 2) ? X2 : X3));
    uint32_t* H = Xh + blockIdx.y * ostride;
    const size_t t = (size_t)blockIdx.x * 256 + threadIdx.x;
    const int row   = (int)(t >> 7);
    const int rem   = (int)(t & 127);
    const int chunk = rem >> 1;
    const int half  = rem & 1;
    float4 v0 = ((const float4*)X)[2*t];
    float4 v1 = ((const float4*)X)[2*t+1];
    uint4 h;
    h.x = pack16(v0.x, v0.y);
    h.y = pack16(v0.z, v0.w);
    h.z = pack16(v1.x, v1.y);
    h.w = pack16(v1.z, v1.w);
    const size_t d = ((size_t)chunk * DD + row) * 2 + half;
    ((uint4*)H)[d] = h;
}

// ---------------------------------------------------------------------------
// gemm_fp16 (R14 winner): D = (Ah + Al) * Wh^T + bias, 2-pass fp16.
// ---------------------------------------------------------------------------
#define GP 136
#define ACH 32768
#define WCH 8192

struct GArg {
    const uint32_t *ah, *al, *wh;
    const float* bias;
    float* c;
};

__global__ __launch_bounds__(256, 2) void gemm_fp16(GArg g0, GArg g1, GArg g2)
{
    GArg g = (blockIdx.z == 0) ? g0 : ((blockIdx.z == 1) ? g1 : g2);
    __shared__ uint32_t Ah[2][8][GP], Al[2][8][GP], Wh[2][8][GP];

    const int tid = threadIdx.x;
    const int bm = blockIdx.y, bn = blockIdx.x;
    const int lane = tid & 31, wid = tid >> 5;
    const int wm = (wid >> 2) * 64;
    const int wn = (wid & 3) * 32;
    const int qrow = lane >> 2, qk = lane & 3;

    const int r = tid >> 1;
    const int k2b = (tid & 1) * 4;

    const uint32_t* AhG = g.ah + ((size_t)(bm*128 + r))*8 + k2b;
    const uint32_t* AlG = g.al + ((size_t)(bm*128 + r))*8 + k2b;
    const uint32_t* WhG = g.wh + ((size_t)(bn*128 + r))*8 + k2b;

    float d[4][4][4];
    #pragma unroll
    for (int mt = 0; mt < 4; mt++)
        #pragma unroll
        for (int nt = 0; nt < 4; nt++)
            #pragma unroll
            for (int i = 0; i < 4; i++) d[mt][nt][i] = 0.f;

    {
        uint4 a = *(const uint4*)AhG;
        uint4 b = *(const uint4*)AlG;
        uint4 c = *(const uint4*)WhG;
        Ah[0][k2b+0][r] = a.x; Ah[0][k2b+1][r] = a.y; Ah[0][k2b+2][r] = a.z; Ah[0][k2b+3][r] = a.w;
        Al[0][k2b+0][r] = b.x; Al[0][k2b+1][r] = b.y; Al[0][k2b+2][r] = b.z; Al[0][k2b+3][r] = b.w;
        Wh[0][k2b+0][r] = c.x; Wh[0][k2b+1][r] = c.y; Wh[0][k2b+2][r] = c.z; Wh[0][k2b+3][r] = c.w;
    }
    __syncthreads();

    int st = 0;
    for (int c = 1; c <= 64; c++) {
        uint4 na, nb, nc;
        const bool has = (c < 64);
        if (has) {
            na = *(const uint4*)(AhG + (size_t)c*ACH);
            nb = *(const uint4*)(AlG + (size_t)c*ACH);
            nc = *(const uint4*)(WhG + (size_t)c*WCH);
        }

        uint32_t afh[4][4], afl[4][4], bfh[4][2];
        #pragma unroll
        for (int mt = 0; mt < 4; mt++) {
            int m0 = wm + mt*16 + qrow;
            #pragma unroll
            for (int i = 0; i < 4; i++) {
                int m  = m0 + ((i & 1) << 3);
                int k2 = qk + ((i >> 1) << 2);
                afh[mt][i] = Ah[st][k2][m];
                afl[mt][i] = Al[st][k2][m];
            }
        }
        #pragma unroll
        for (int nt = 0; nt < 4; nt++) {
            int n0 = wn + nt*8 + qrow;
            #pragma unroll
            for (int i = 0; i < 2; i++)
                bfh[nt][i] = Wh[st][qk + 4*i][n0];
        }

        #pragma unroll
        for (int mt = 0; mt < 4; mt++)
            #pragma unroll
            for (int nt = 0; nt < 4; nt++) {
                MMA_F16(d[mt][nt], afh[mt], bfh[nt]);
                MMA_F16(d[mt][nt], afl[mt], bfh[nt]);
            }

        if (has) {
            int s2 = st ^ 1;
            Ah[s2][k2b+0][r] = na.x; Ah[s2][k2b+1][r] = na.y; Ah[s2][k2b+2][r] = na.z; Ah[s2][k2b+3][r] = na.w;
            Al[s2][k2b+0][r] = nb.x; Al[s2][k2b+1][r] = nb.y; Al[s2][k2b+2][r] = nb.z; Al[s2][k2b+3][r] = nb.w;
            Wh[s2][k2b+0][r] = nc.x; Wh[s2][k2b+1][r] = nc.y; Wh[s2][k2b+2][r] = nc.z; Wh[s2][k2b+3][r] = nc.w;
        }
        __syncthreads();
        st ^= 1;
    }

    #pragma unroll
    for (int mt = 0; mt < 4; mt++)
        #pragma unroll
        for (int nt = 0; nt < 4; nt++) {
            int col0 = bn*128 + wn + nt*8 + 2*qk;
            float b0 = g.bias[col0], b1 = g.bias[col0+1];
            #pragma unroll
            for (int half = 0; half < 2; half++) {
                int row = bm*128 + wm + mt*16 + qrow + 8*half;
                float2 v;
                v.x = d[mt][nt][2*half+0] + b0;
                v.y = d[mt][nt][2*half+1] + b1;
                *(float2*)&g.c[(size_t)row*DD + col0] = v;
            }
        }
}

// ---------------------------------------------------------------------------
// RoPE + head-transpose + fp16 packing.
// Q (blockIdx.y==0): exact fp16 hi+lo, scale (1/8)*log2(e).
// K (blockIdx.y==1): fp16 single.
// ---------------------------------------------------------------------------
__global__ __launch_bounds__(256) void rope_split(
    const float* __restrict__ qlin, const float* __restrict__ klin,
    const float* __restrict__ cosT, const float* __restrict__ sinT,
    uint32_t* __restrict__ qh, uint32_t* __restrict__ ql,
    uint32_t* __restrict__ kh)
{
    const int t = blockIdx.x * 256 + threadIdx.x;
    const int isK = blockIdx.y;
    const float* src = isK ? klin : qlin;
    const float scale = isK ? 1.0f : 0.18033688011112042f;  // 0.125*log2(e)

    const int k2 = t & 15;
    const int s  = (t >> 4) & (SS - 1);
    const int bh = t >> 15;
    const int b = bh >> 4, h = bh & 15;
    const int j0 = 2*k2, j1 = 2*k2 + 1;

    const float* sp = src + ((size_t)(b*SS + s))*DD + h*DK;
    float x0 = sp[j0],      x1 = sp[j1];
    float y0 = sp[j0 + 32], y1 = sp[j1 + 32];
    float c0 = cosT[s*32 + j0], c1 = cosT[s*32 + j1];
    float s0 = sinT[s*32 + j0], s1 = sinT[s*32 + j1];

    float o0 = (x0*c0 - y0*s0) * scale;
    float o1 = (x1*c1 - y1*s1) * scale;
    float p0 = (y0*c0 + x0*s0) * scale;
    float p1 = (y1*c1 + x1*s1) * scale;

    size_t base = ((size_t)bh*SS + s)*32;
    if (isK) {
        kh[base + k2]      = pack16(o0, o1);
        kh[base + k2 + 16] = pack16(p0, p1);
    } else {
        float r0, r1;
        uint32_t hv = pack_hi16(o0, o1, r0, r1);
        qh[base + k2] = hv;            ql[base + k2] = pack_lo16(r0, r1);
        hv = pack_hi16(p0, p1, r0, r1);
        qh[base + k2 + 16] = hv;       ql[base + k2 + 16] = pack_lo16(r0, r1);
    }
}

// ---------------------------------------------------------------------------
// V: fp16 single, packed along key pairs: vh[bh][kp][d] = h2(V[2kp][d], V[2kp+1][d])
// ---------------------------------------------------------------------------
__global__ __launch_bounds__(256) void v_split(
    const float* __restrict__ vlin, uint32_t* __restrict__ vh)
{
    const int t = blockIdx.x * 256 + threadIdx.x;
    const int d4 = (t & 15) * 4;
    const int kp = (t >> 4) & 1023;
    const int bh = t >> 14;
    const int b = bh >> 4, h = bh & 15;

    const float* r0p = vlin + ((size_t)(b*SS + 2*kp))*DD + h*DK + d4;
    float4 a = *(const float4*)r0p;
    float4 c = *(const float4*)(r0p + DD);

    uint4 hh;
    hh.x = pack16(a.x, c.x);
    hh.y = pack16(a.y, c.y);
    hh.z = pack16(a.z, c.z);
    hh.w = pack16(a.w, c.w);

    size_t base = ((size_t)bh*1024 + kp)*64 + d4;
    *(uint4*)&vh[base] = hh;
}

// ---------------------------------------------------------------------------
// Flash v6: fp16 2+2 passes. Q exact hi+lo x K-single (QK), P exact hi+lo x
// V-single (PV). No-max softmax (2^s via ex2), cp.async double-buffered K/V.
// smem (u32): Qh 0 (4608), Ql 4608 (4608), Kh[st] 9216+st*2304,
//             Vh[st] 13824+st*2304. Total 18432 u32 = 73728 B.
// ---------------------------------------------------------------------------
#define QP 36
#define VP 72
#define FLASH_SMEM (18432*4)

__global__ __launch_bounds__(256, 2) void flash_tc6(
    const uint32_t* __restrict__ qh_g, const uint32_t* __restrict__ ql_g,
    const uint32_t* __restrict__ kh_g, const uint32_t* __restrict__ vh_g,
    uint32_t* __restrict__ cth, uint32_t* __restrict__ ctl)
{
    extern __shared__ uint32_t smu[];
    const uint32_t sbase = (uint32_t)__cvta_generic_to_shared(smu);

    const int tid = threadIdx.x;
    const int qi = 15 - blockIdx.x;
    const int bh = blockIdx.y;
    const int b = bh >> 4, h = bh & 15;
    const int lane = tid & 31, wid = tid >> 5;
    const int qk = lane & 3, qrow = lane >> 2;
    const int wr = wid * 16;
    const int nkt = 2*qi + 2;

    const int krow = tid >> 2, kk2b = (tid & 3) * 8;
    const int vkp  = tid >> 3, vdb  = (tid & 7) * 8;
    const size_t kgo = ((size_t)bh*SS + krow)*32 + kk2b;
    const size_t vgo = ((size_t)bh*1024 + vkp)*64 + vdb;

    // ---- prologue: Q hi+lo ----
    {
        const int row = tid >> 1, cb = (tid & 1) * 16;
        const uint32_t* sh = qh_g + ((size_t)bh*SS + qi*128 + row)*32 + cb;
        const uint32_t* sl = ql_g + ((size_t)bh*SS + qi*128 + row)*32 + cb;
        uint32_t dh = sbase + (row*QP + cb)*4;
        uint32_t dl = sbase + (4608 + row*QP + cb)*4;
        CPA16(dh,    sh);     CPA16(dh+16, sh+4);
        CPA16(dh+32, sh+8);   CPA16(dh+48, sh+12);
        CPA16(dl,    sl);     CPA16(dl+16, sl+4);
        CPA16(dl+32, sl+8);   CPA16(dl+48, sl+12);
    }
    CPA_COMMIT();

    // ---- prologue: K/V stages 0,1 ----
    #pragma unroll
    for (int pk = 0; pk < 2; pk++) {
        uint32_t kh_d = sbase + (9216  + pk*2304 + krow*QP + kk2b)*4;
        uint32_t vh_d = sbase + (13824 + pk*2304 + vkp*VP + vdb)*4;
        const uint32_t* skh = kh_g + kgo + (size_t)pk*64*32;
        const uint32_t* svh = vh_g + vgo + (size_t)pk*32*64;
        CPA16(kh_d, skh);  CPA16(kh_d+16, skh+4);
        CPA16(vh_d, svh);  CPA16(vh_d+16, svh+4);
        CPA_COMMIT();
    }

    float l0 = 0.f, l1 = 0.f;
    float of[8][4];
    #pragma unroll
    for (int nt = 0; nt < 8; nt++)
        #pragma unroll
        for (int i = 0; i < 4; i++) of[nt][i] = 0.f;

    const uint32_t* QhS = smu;
    const uint32_t* QlS = smu + 4608;

    for (int kt = 0; kt < nkt; kt++) {
        const int st = kt & 1;
        if (kt + 1 < nkt) { CPA_WAIT(1); } else { CPA_WAIT(0); }
        __syncthreads();

        const uint32_t* KhS = smu + 9216  + st*2304;
        const uint32_t* VhS = smu + 13824 + st*2304;

        // ---- S = Q K^T (2 passes: Qh, Ql) ----
        float sf[8][4];
        #pragma unroll
        for (int nt = 0; nt < 8; nt++)
            #pragma unroll
            for (int i = 0; i < 4; i++) sf[nt][i] = 0.f;

        #pragma unroll
        for (int kc = 0; kc < 4; kc++) {
            uint32_t ah[4], al[4];
            const int k2a = qk + 8*kc, k2c = k2a + 4;
            const int r0o = (wr + qrow)*QP, r1o = (wr + qrow + 8)*QP;
            ah[0] = QhS[r0o + k2a]; ah[1] = QhS[r1o + k2a];
            ah[2] = QhS[r0o + k2c]; ah[3] = QhS[r1o + k2c];
            al[0] = QlS[r0o + k2a]; al[1] = QlS[r1o + k2a];
            al[2] = QlS[r0o + k2c]; al[3] = QlS[r1o + k2c];
            #pragma unroll
            for (int nt = 0; nt < 8; nt++) {
                const int co = (nt*8 + qrow)*QP;
                uint32_t bb[2] = { KhS[co + k2a], KhS[co + k2c] };
                MMA_F16(sf[nt], ah, bb);
            }
            #pragma unroll
            for (int nt = 0; nt < 8; nt++) {
                const int co = (nt*8 + qrow)*QP;
                uint32_t bb[2] = { KhS[co + k2a], KhS[co + k2c] };
                MMA_F16(sf[nt], al, bb);
            }
        }

        // ---- causal mask ----
        if (kt >= 2*qi) {
            #pragma unroll
            for (int nt = 0; nt < 8; nt++) {
                #pragma unroll
                for (int i = 0; i < 4; i++) {
                    int col_g = kt*64 + nt*8 + 2*qk + (i & 1);
                    int row_g = qi*128 + wr + qrow + 8*(i >> 1);
                    if (col_g > row_g) sf[nt][i] = -1e30f;
                }
            }
        }

        // ---- softmax numerators: P = 2^s ----
        #pragma unroll
        for (int nt = 0; nt < 8; nt++) {
            sf[nt][0] = ex2(sf[nt][0]);
            sf[nt][1] = ex2(sf[nt][1]);
            sf[nt][2] = ex2(sf[nt][2]);
            sf[nt][3] = ex2(sf[nt][3]);
            l0 += sf[nt][0] + sf[nt][1];
            l1 += sf[nt][2] + sf[nt][3];
        }

        // ---- O += P V (2 passes: Ph, Pl) ----
        #pragma unroll
        for (int kc = 0; kc < 4; kc++) {
            uint32_t pah[4], pal[4];
            float r0, r1;
            pah[0] = pack_hi16(sf[2*kc][0],   sf[2*kc][1],   r0, r1); pal[0] = pack_lo16(r0, r1);
            pah[1] = pack_hi16(sf[2*kc][2],   sf[2*kc][3],   r0, r1); pal[1] = pack_lo16(r0, r1);
            pah[2] = pack_hi16(sf[2*kc+1][0], sf[2*kc+1][1], r0, r1); pal[2] = pack_lo16(r0, r1);
            pah[3] = pack_hi16(sf[2*kc+1][2], sf[2*kc+1][3], r0, r1); pal[3] = pack_lo16(r0, r1);
            const int kpa = 8*kc + qk, kpc = kpa + 4;
            #pragma unroll
            for (int nt = 0; nt < 8; nt++) {
                const int col = nt*8 + qrow;
                uint32_t bb[2] = { VhS[kpa*VP + col], VhS[kpc*VP + col] };
                MMA_F16(of[nt], pah, bb);
            }
            #pragma unroll
            for (int nt = 0; nt < 8; nt++) {
                const int col = nt*8 + qrow;
                uint32_t bb[2] = { VhS[kpa*VP + col], VhS[kpc*VP + col] };
                MMA_F16(of[nt], pal, bb);
            }
        }

        __syncthreads();

        // ---- prefetch kt+2 ----
        if (kt + 2 < nkt) {
            const int nk = kt + 2;
            uint32_t kh_d = sbase + (9216  + st*2304 + krow*QP + kk2b)*4;
            uint32_t vh_d = sbase + (13824 + st*2304 + vkp*VP + vdb)*4;
            const uint32_t* skh = kh_g + kgo + (size_t)nk*64*32;
            const uint32_t* svh = vh_g + vgo + (size_t)nk*32*64;
            CPA16(kh_d, skh);  CPA16(kh_d+16, skh+4);
            CPA16(vh_d, svh);  CPA16(vh_d+16, svh+4);
            CPA_COMMIT();
        }
    }

    l0 += __shfl_xor_sync(0xffffffffu, l0, 1);
    l0 += __shfl_xor_sync(0xffffffffu, l0, 2);
    l1 += __shfl_xor_sync(0xffffffffu, l1, 1);
    l1 += __shfl_xor_sync(0xffffffffu, l1, 2);

    float inv0 = 1.f / l0, inv1 = 1.f / l1;
    #pragma unroll
    for (int nt = 0; nt < 8; nt++) {
        const int k2g = h*32 + nt*4 + qk;
        const int chn = k2g >> 3, wix = k2g & 7;
        const int row0 = b*SS + qi*128 + wr + qrow;
        float r0, r1;
        uint32_t hv = pack_hi16(of[nt][0]*inv0, of[nt][1]*inv0, r0, r1);
        size_t di = ((size_t)chn*MROWS + row0)*8 + wix;
        cth[di] = hv;
        ctl[di] = pack_lo16(r0, r1);
        hv = pack_hi16(of[nt][2]*inv1, of[nt][3]*inv1, r0, r1);
        di = ((size_t)chn*MROWS + row0 + 8)*8 + wix;
        cth[di] = hv;
        ctl[di] = pack_lo16(r0, r1);
    }
}

// ---------------------------------------------------------------------------
extern "C" void kernel_launch(void* const* d_in, const int* in_sizes, int n_in,
                              void* d_out, int out_size)
{
    (void)in_sizes; (void)n_in; (void)out_size;
    const float* query = (const float*)d_in[0];
    const float* key   = (const float*)d_in[1];
    const float* value = (const float*)d_in[2];
    const float* Wq = (const float*)d_in[4];
    const float* bq = (const float*)d_in[5];
    const float* Wk = (const float*)d_in[6];
    const float* bk = (const float*)d_in[7];
    const float* Wv = (const float*)d_in[8];
    const float* bv = (const float*)d_in[9];
    const float* Wo = (const float*)d_in[10];
    const float* bo = (const float*)d_in[11];
    float* out = (float*)d_out;

    float *qlin, *klin, *vlin, *cosT, *sinT;
    uint32_t *qh, *ql, *kh, *vh;
    uint32_t *ah, *al, *wh, *cth, *ctl;
    cudaGetSymbolAddress((void**)&qlin, g_qlin);
    cudaGetSymbolAddress((void**)&klin, g_klin);
    cudaGetSymbolAddress((void**)&vlin, g_vlin);
    cudaGetSymbolAddress((void**)&cosT, g_cos);
    cudaGetSymbolAddress((void**)&sinT, g_sin);
    cudaGetSymbolAddress((void**)&qh, g_qh);
    cudaGetSymbolAddress((void**)&ql, g_ql);
    cudaGetSymbolAddress((void**)&kh, g_kh);
    cudaGetSymbolAddress((void**)&vh, g_vh);
    cudaGetSymbolAddress((void**)&ah, g_ah);
    cudaGetSymbolAddress((void**)&al, g_al);
    cudaGetSymbolAddress((void**)&wh, g_wh);
    cudaGetSymbolAddress((void**)&cth, g_cth);
    cudaGetSymbolAddress((void**)&ctl, g_ctl);

    const size_t ASTRIDE = (size_t)MROWS*512;
    const size_t WSTRIDE = (size_t)DD*512;

    cudaFuncSetAttribute(flash_tc6, cudaFuncAttributeMaxDynamicSharedMemorySize, FLASH_SMEM);

    rope_tables<<<SS*32/256, 256>>>(cosT, sinT);

    const int ABLK = MROWS*DD/8/256;   // 2048
    const int WBLK = DD*DD/8/256;      // 512
    dim3 sp3Grid(ABLK, 3);
    split_act3<<<sp3Grid, 256>>>(query, key, value, ah, al, ASTRIDE);
    dim3 sp4Grid(WBLK, 4);
    split_w4<<<sp4Grid, 256>>>(Wq, Wk, Wv, Wo, wh, WSTRIDE);

    GArg gq = { ah + 0*ASTRIDE, al + 0*ASTRIDE, wh + 0*WSTRIDE, bq, qlin };
    GArg gk = { ah + 1*ASTRIDE, al + 1*ASTRIDE, wh + 1*WSTRIDE, bk, klin };
    GArg gv = { ah + 2*ASTRIDE, al + 2*ASTRIDE, wh + 2*WSTRIDE, bv, vlin };
    dim3 gemmGrid(DD/128, MROWS/128, 3);
    gemm_fp16<<<gemmGrid, 256>>>(gq, gk, gv);

    dim3 rsGrid((BB*HH*SS*16)/256, 2);
    rope_split<<<rsGrid, 256>>>(qlin, klin, cosT, sinT, qh, ql, kh);
    v_split<<<(BB*HH*1024*16)/256, 256>>>(vlin, vh);

    dim3 faGrid(SS/128, BB*HH);            // (16, 32)
    flash_tc6<<<faGrid, 256, FLASH_SMEM>>>(qh, ql, kh, vh, cth, ctl);

    GArg go = { cth, ctl, wh + 3*WSTRIDE, bo, out };
    dim3 gemmGridO(DD/128, MROWS/128, 1);
    gemm_fp16<<<gemmGridO, 256>>>(go, go, go);
}

// round 16
// speedup vs baseline: 1.4290x; 1.0366x over previous
#include <cuda_runtime.h>
#include <cuda_bf16.h>
#include <cuda_fp16.h>
#include <math.h>
#include <stdint.h>

#define BB 2
#define SS 2048
#define DD 1024
#define HH 16
#define DK 64
#define MROWS (BB*SS)   // 4096

// Scratch (device globals — allocation is forbidden)
__device__ float g_qlin[MROWS*DD];
__device__ float g_klin[MROWS*DD];
__device__ float g_vlin[MROWS*DD];
__device__ float g_cos[SS*32];
__device__ float g_sin[SS*32];
// fp16 packed operands for flash: u32 = packed half2
__device__ uint32_t g_qh[BB*HH*SS*32];    // Q fp16 hi
__device__ uint32_t g_ql[BB*HH*SS*32];    // Q fp16 lo (exact residual)
__device__ uint32_t g_kh[BB*HH*SS*32];    // K fp16 (single)
__device__ uint32_t g_vh[BB*HH*(SS/2)*DK];// V fp16 (single), key-pair packed
// fp16-split GEMM operands, CHUNK-MAJOR blocked: [chunk64][rows][8 u32]
__device__ uint32_t g_ah[3][MROWS*512];   // activation fp16 hi
__device__ uint32_t g_al[3][MROWS*512];   // activation fp16 lo
__device__ uint32_t g_wh[4][DD*512];      // weight fp16 (single)
__device__ uint32_t g_cth[MROWS*512];     // ctx fp16 hi
__device__ uint32_t g_ctl[MROWS*512];     // ctx fp16 lo

// ---------------------------------------------------------------------------
__device__ __forceinline__ uint32_t pack_hi16(float a, float b, float& ra, float& rb)
{
    __half ha = __float2half_rn(a);
    __half hb = __float2half_rn(b);
    ra = a - __half2float(ha);
    rb = b - __half2float(hb);
    __half2 p; p.x = ha; p.y = hb;
    return *reinterpret_cast<uint32_t*>(&p);
}
__device__ __forceinline__ uint32_t pack_lo16(float ra, float rb)
{
    __half2 p = __floats2half2_rn(ra, rb);
    return *reinterpret_cast<uint32_t*>(&p);
}
__device__ __forceinline__ uint32_t pack16(float a, float b)
{
    __half2 p = __floats2half2_rn(a, b);
    return *reinterpret_cast<uint32_t*>(&p);
}
__device__ __forceinline__ float ex2(float x)
{
    float r;
    asm("ex2.approx.f32 %0, %1;" : "=f"(r) : "f"(x));
    return r;
}

#define MMA_F16(d, a, b) \
    asm volatile("mma.sync.aligned.m16n8k16.row.col.f32.f16.f16.f32 " \
        "{%0,%1,%2,%3}, {%4,%5,%6,%7}, {%8,%9}, {%0,%1,%2,%3};" \
        : "+f"(d[0]), "+f"(d[1]), "+f"(d[2]), "+f"(d[3]) \
        : "r"(a[0]), "r"(a[1]), "r"(a[2]), "r"(a[3]), "r"(b[0]), "r"(b[1]))

#define CPA16(dst, src)  asm volatile("cp.async.cg.shared.global [%0], [%1], 16;" :: "r"(dst), "l"(src))
#define CPA_COMMIT()     asm volatile("cp.async.commit_group;" ::: "memory")
#define CPA_WAIT(N)      asm volatile("cp.async.wait_group %0;" :: "n"(N) : "memory")

// ---------------------------------------------------------------------------
__global__ __launch_bounds__(256) void rope_tables(float* cosT, float* sinT)
{
    const int t = blockIdx.x * 256 + threadIdx.x;
    const int j = t & 31;
    const int s = t >> 5;
    double inv = exp(-(double)j * 0.28782313662425575);
    double sd, cd;
    sincos((double)s * inv, &sd, &cd);
    cosT[t] = (float)cd;
    sinT[t] = (float)sd;
}

// ---------------------------------------------------------------------------
// Activations: fp16 hi+lo, chunk-major blocked.
// ---------------------------------------------------------------------------
__global__ __launch_bounds__(256) void split_act3(
    const float* __restrict__ X0, const float* __restrict__ X1,
    const float* __restrict__ X2,
    uint32_t* __restrict__ Xh, uint32_t* __restrict__ Xl, size_t ostride)
{
    const float* X = (blockIdx.y == 0) ? X0 : ((blockIdx.y == 1) ? X1 : X2);
    uint32_t* H = Xh + blockIdx.y * ostride;
    uint32_t* L = Xl + blockIdx.y * ostride;
    const size_t t = (size_t)blockIdx.x * 256 + threadIdx.x;
    const int row   = (int)(t >> 7);
    const int rem   = (int)(t & 127);
    const int chunk = rem >> 1;
    const int half  = rem & 1;
    float4 v0 = ((const float4*)X)[2*t];
    float4 v1 = ((const float4*)X)[2*t+1];
    float r0, r1, r2, r3, r4, r5, r6, r7;
    uint4 h, l;
    h.x = pack_hi16(v0.x, v0.y, r0, r1);
    h.y = pack_hi16(v0.z, v0.w, r2, r3);
    h.z = pack_hi16(v1.x, v1.y, r4, r5);
    h.w = pack_hi16(v1.z, v1.w, r6, r7);
    l.x = pack_lo16(r0, r1); l.y = pack_lo16(r2, r3);
    l.z = pack_lo16(r4, r5); l.w = pack_lo16(r6, r7);
    const size_t d = ((size_t)chunk * MROWS + row) * 2 + half;
    ((uint4*)H)[d] = h;
    ((uint4*)L)[d] = l;
}

// Weights: fp16 single, chunk-major blocked.
__global__ __launch_bounds__(256) void split_w4(
    const float* __restrict__ X0, const float* __restrict__ X1,
    const float* __restrict__ X2, const float* __restrict__ X3,
    uint32_t* __restrict__ Xh, size_t ostride)
{
    const float* X = (blockIdx.y == 0) ? X0 : ((blockIdx.y == 1) ? X1 :
                     ((blockIdx.y == 2) ? X2 : X3));
    uint32_t* H = Xh + blockIdx.y * ostride;
    const size_t t = (size_t)blockIdx.x * 256 + threadIdx.x;
    const int row   = (int)(t >> 7);
    const int rem   = (int)(t & 127);
    const int chunk = rem >> 1;
    const int half  = rem & 1;
    float4 v0 = ((const float4*)X)[2*t];
    float4 v1 = ((const float4*)X)[2*t+1];
    uint4 h;
    h.x = pack16(v0.x, v0.y);
    h.y = pack16(v0.z, v0.w);
    h.z = pack16(v1.x, v1.y);
    h.w = pack16(v1.z, v1.w);
    const size_t d = ((size_t)chunk * DD + row) * 2 + half;
    ((uint4*)H)[d] = h;
}

// ---------------------------------------------------------------------------
// gemm_fp16b: 2-pass fp16 GEMM, BK=32, 32x64 warp tiles (frag traffic -20%,
// syncs halved vs BK=16/64x32). Row-major pitch-20 smem: frag banks
// (20*qrow + qk)%32 all-distinct. Double-buffered LDG+STS (uint4) pipeline.
// Stage layout (u32): Ah @0, Al @GA, Wh @2*GA; word = row*20 + k2.
// ---------------------------------------------------------------------------
#define GP2 20
#define GA  (128*GP2)       // 2560 u32 per array
#define GSTG2 (3*GA)        // 7680 u32 per stage
#define GEMM_SMEM (2*GSTG2*4)  // 61440 B
#define ACH 32768
#define WCH 8192

struct GArg {
    const uint32_t *ah, *al, *wh;
    const float* bias;
    float* c;
};

__global__ __launch_bounds__(256, 2) void gemm_fp16b(GArg g0, GArg g1, GArg g2)
{
    extern __shared__ uint32_t gsm[];
    GArg g = (blockIdx.z == 0) ? g0 : ((blockIdx.z == 1) ? g1 : g2);

    const int tid = threadIdx.x;
    const int bm = blockIdx.y, bn = blockIdx.x;
    const int lane = tid & 31, wid = tid >> 5;
    const int wm = (wid & 3) * 32;      // 4 warp rows x 32
    const int wn = (wid >> 2) * 64;     // 2 warp cols x 64
    const int qrow = lane >> 2, qk = lane & 3;

    const int r = tid >> 1;
    const int x = tid & 1;

    const uint32_t* AhG = g.ah + (size_t)(bm*128 + r)*8 + 4*x;
    const uint32_t* AlG = g.al + (size_t)(bm*128 + r)*8 + 4*x;
    const uint32_t* WhG = g.wh + (size_t)(bn*128 + r)*8 + 4*x;
    const int dA = r*GP2 + 4*x;   // + 8*par ; Al: +GA; Wh: +2*GA; + stage*GSTG2

    float d[2][8][4];
    #pragma unroll
    for (int mt = 0; mt < 2; mt++)
        #pragma unroll
        for (int nt = 0; nt < 8; nt++)
            #pragma unroll
            for (int i = 0; i < 4; i++) d[mt][nt][i] = 0.f;

    // prologue: chunks 0,1 -> stage 0
    {
        uint4 a0 = *(const uint4*)(AhG);
        uint4 a1 = *(const uint4*)(AhG + ACH);
        uint4 b0 = *(const uint4*)(AlG);
        uint4 b1 = *(const uint4*)(AlG + ACH);
        uint4 c0 = *(const uint4*)(WhG);
        uint4 c1 = *(const uint4*)(WhG + WCH);
        *(uint4*)&gsm[dA]          = a0;  *(uint4*)&gsm[dA + 8]          = a1;
        *(uint4*)&gsm[GA + dA]     = b0;  *(uint4*)&gsm[GA + dA + 8]     = b1;
        *(uint4*)&gsm[2*GA + dA]   = c0;  *(uint4*)&gsm[2*GA + dA + 8]   = c1;
    }
    __syncthreads();

    int st = 0;
    for (int c = 1; c <= 32; c++) {    // 32 iterations of BK=32
        uint4 na0, na1, nb0, nb1, nc0, nc1;
        const bool has = (c < 32);
        if (has) {
            na0 = *(const uint4*)(AhG + (size_t)(2*c)*ACH);
            na1 = *(const uint4*)(AhG + (size_t)(2*c+1)*ACH);
            nb0 = *(const uint4*)(AlG + (size_t)(2*c)*ACH);
            nb1 = *(const uint4*)(AlG + (size_t)(2*c+1)*ACH);
            nc0 = *(const uint4*)(WhG + (size_t)(2*c)*WCH);
            nc1 = *(const uint4*)(WhG + (size_t)(2*c+1)*WCH);
        }

        const uint32_t* S = gsm + st*GSTG2;

        #pragma unroll
        for (int kk = 0; kk < 2; kk++) {
            uint32_t afh[2][4], afl[2][4], bfh[8][2];
            #pragma unroll
            for (int mt = 0; mt < 2; mt++) {
                const int m0 = wm + mt*16 + qrow;
                #pragma unroll
                for (int i = 0; i < 4; i++) {
                    const int m  = m0 + ((i & 1) << 3);
                    const int k2 = qk + ((i >> 1) << 2) + 8*kk;
                    afh[mt][i] = S[m*GP2 + k2];
                    afl[mt][i] = S[GA + m*GP2 + k2];
                }
            }
            #pragma unroll
            for (int nt = 0; nt < 8; nt++) {
                const int n0 = wn + nt*8 + qrow;
                #pragma unroll
                for (int i = 0; i < 2; i++)
                    bfh[nt][i] = S[2*GA + n0*GP2 + qk + 4*i + 8*kk];
            }
            #pragma unroll
            for (int mt = 0; mt < 2; mt++)
                #pragma unroll
                for (int nt = 0; nt < 8; nt++) {
                    MMA_F16(d[mt][nt], afh[mt], bfh[nt]);
                    MMA_F16(d[mt][nt], afl[mt], bfh[nt]);
                }
        }

        if (has) {
            uint32_t* T = gsm + (st ^ 1)*GSTG2;
            *(uint4*)&T[dA]        = na0;  *(uint4*)&T[dA + 8]        = na1;
            *(uint4*)&T[GA + dA]   = nb0;  *(uint4*)&T[GA + dA + 8]   = nb1;
            *(uint4*)&T[2*GA + dA] = nc0;  *(uint4*)&T[2*GA + dA + 8] = nc1;
        }
        __syncthreads();
        st ^= 1;
    }

    #pragma unroll
    for (int mt = 0; mt < 2; mt++)
        #pragma unroll
        for (int nt = 0; nt < 8; nt++) {
            int col0 = bn*128 + wn + nt*8 + 2*qk;
            float b0 = g.bias[col0], b1 = g.bias[col0+1];
            #pragma unroll
            for (int half = 0; half < 2; half++) {
                int row = bm*128 + wm + mt*16 + qrow + 8*half;
                float2 v;
                v.x = d[mt][nt][2*half+0] + b0;
                v.y = d[mt][nt][2*half+1] + b1;
                *(float2*)&g.c[(size_t)row*DD + col0] = v;
            }
        }
}

// ---------------------------------------------------------------------------
// RoPE + head-transpose + fp16 packing. Q: exact hi+lo, scale (1/8)*log2(e);
// K: fp16 single.
// ---------------------------------------------------------------------------
__global__ __launch_bounds__(256) void rope_split(
    const float* __restrict__ qlin, const float* __restrict__ klin,
    const float* __restrict__ cosT, const float* __restrict__ sinT,
    uint32_t* __restrict__ qh, uint32_t* __restrict__ ql,
    uint32_t* __restrict__ kh)
{
    const int t = blockIdx.x * 256 + threadIdx.x;
    const int isK = blockIdx.y;
    const float* src = isK ? klin : qlin;
    const float scale = isK ? 1.0f : 0.18033688011112042f;  // 0.125*log2(e)

    const int k2 = t & 15;
    const int s  = (t >> 4) & (SS - 1);
    const int bh = t >> 15;
    const int b = bh >> 4, h = bh & 15;
    const int j0 = 2*k2, j1 = 2*k2 + 1;

    const float* sp = src + ((size_t)(b*SS + s))*DD + h*DK;
    float x0 = sp[j0],      x1 = sp[j1];
    float y0 = sp[j0 + 32], y1 = sp[j1 + 32];
    float c0 = cosT[s*32 + j0], c1 = cosT[s*32 + j1];
    float s0 = sinT[s*32 + j0], s1 = sinT[s*32 + j1];

    float o0 = (x0*c0 - y0*s0) * scale;
    float o1 = (x1*c1 - y1*s1) * scale;
    float p0 = (y0*c0 + x0*s0) * scale;
    float p1 = (y1*c1 + x1*s1) * scale;

    size_t base = ((size_t)bh*SS + s)*32;
    if (isK) {
        kh[base + k2]      = pack16(o0, o1);
        kh[base + k2 + 16] = pack16(p0, p1);
    } else {
        float r0, r1;
        uint32_t hv = pack_hi16(o0, o1, r0, r1);
        qh[base + k2] = hv;            ql[base + k2] = pack_lo16(r0, r1);
        hv = pack_hi16(p0, p1, r0, r1);
        qh[base + k2 + 16] = hv;       ql[base + k2 + 16] = pack_lo16(r0, r1);
    }
}

// ---------------------------------------------------------------------------
__global__ __launch_bounds__(256) void v_split(
    const float* __restrict__ vlin, uint32_t* __restrict__ vh)
{
    const int t = blockIdx.x * 256 + threadIdx.x;
    const int d4 = (t & 15) * 4;
    const int kp = (t >> 4) & 1023;
    const int bh = t >> 14;
    const int b = bh >> 4, h = bh & 15;

    const float* r0p = vlin + ((size_t)(b*SS + 2*kp))*DD + h*DK + d4;
    float4 a = *(const float4*)r0p;
    float4 c = *(const float4*)(r0p + DD);

    uint4 hh;
    hh.x = pack16(a.x, c.x);
    hh.y = pack16(a.y, c.y);
    hh.z = pack16(a.z, c.z);
    hh.w = pack16(a.w, c.w);

    size_t base = ((size_t)bh*1024 + kp)*64 + d4;
    *(uint4*)&vh[base] = hh;
}

// ---------------------------------------------------------------------------
// Flash v6 (R15 winner): fp16 2+2 passes, no-max softmax, cp.async K/V.
// ---------------------------------------------------------------------------
#define QP 36
#define VP 72
#define FLASH_SMEM (18432*4)

__global__ __launch_bounds__(256, 2) void flash_tc6(
    const uint32_t* __restrict__ qh_g, const uint32_t* __restrict__ ql_g,
    const uint32_t* __restrict__ kh_g, const uint32_t* __restrict__ vh_g,
    uint32_t* __restrict__ cth, uint32_t* __restrict__ ctl)
{
    extern __shared__ uint32_t smu[];
    const uint32_t sbase = (uint32_t)__cvta_generic_to_shared(smu);

    const int tid = threadIdx.x;
    const int qi = 15 - blockIdx.x;
    const int bh = blockIdx.y;
    const int b = bh >> 4, h = bh & 15;
    const int lane = tid & 31, wid = tid >> 5;
    const int qk = lane & 3, qrow = lane >> 2;
    const int wr = wid * 16;
    const int nkt = 2*qi + 2;

    const int krow = tid >> 2, kk2b = (tid & 3) * 8;
    const int vkp  = tid >> 3, vdb  = (tid & 7) * 8;
    const size_t kgo = ((size_t)bh*SS + krow)*32 + kk2b;
    const size_t vgo = ((size_t)bh*1024 + vkp)*64 + vdb;

    {
        const int row = tid >> 1, cb = (tid & 1) * 16;
        const uint32_t* sh = qh_g + ((size_t)bh*SS + qi*128 + row)*32 + cb;
        const uint32_t* sl = ql_g + ((size_t)bh*SS + qi*128 + row)*32 + cb;
        uint32_t dh = sbase + (row*QP + cb)*4;
        uint32_t dl = sbase + (4608 + row*QP + cb)*4;
        CPA16(dh,    sh);     CPA16(dh+16, sh+4);
        CPA16(dh+32, sh+8);   CPA16(dh+48, sh+12);
        CPA16(dl,    sl);     CPA16(dl+16, sl+4);
        CPA16(dl+32, sl+8);   CPA16(dl+48, sl+12);
    }
    CPA_COMMIT();

    #pragma unroll
    for (int pk = 0; pk < 2; pk++) {
        uint32_t kh_d = sbase + (9216  + pk*2304 + krow*QP + kk2b)*4;
        uint32_t vh_d = sbase + (13824 + pk*2304 + vkp*VP + vdb)*4;
        const uint32_t* skh = kh_g + kgo + (size_t)pk*64*32;
        const uint32_t* svh = vh_g + vgo + (size_t)pk*32*64;
        CPA16(kh_d, skh);  CPA16(kh_d+16, skh+4);
        CPA16(vh_d, svh);  CPA16(vh_d+16, svh+4);
        CPA_COMMIT();
    }

    float l0 = 0.f, l1 = 0.f;
    float of[8][4];
    #pragma unroll
    for (int nt = 0; nt < 8; nt++)
        #pragma unroll
        for (int i = 0; i < 4; i++) of[nt][i] = 0.f;

    const uint32_t* QhS = smu;
    const uint32_t* QlS = smu + 4608;

    for (int kt = 0; kt < nkt; kt++) {
        const int st = kt & 1;
        if (kt + 1 < nkt) { CPA_WAIT(1); } else { CPA_WAIT(0); }
        __syncthreads();

        const uint32_t* KhS = smu + 9216  + st*2304;
        const uint32_t* VhS = smu + 13824 + st*2304;

        float sf[8][4];
        #pragma unroll
        for (int nt = 0; nt < 8; nt++)
            #pragma unroll
            for (int i = 0; i < 4; i++) sf[nt][i] = 0.f;

        #pragma unroll
        for (int kc = 0; kc < 4; kc++) {
            uint32_t ah[4], al[4];
            const int k2a = qk + 8*kc, k2c = k2a + 4;
            const int r0o = (wr + qrow)*QP, r1o = (wr + qrow + 8)*QP;
            ah[0] = QhS[r0o + k2a]; ah[1] = QhS[r1o + k2a];
            ah[2] = QhS[r0o + k2c]; ah[3] = QhS[r1o + k2c];
            al[0] = QlS[r0o + k2a]; al[1] = QlS[r1o + k2a];
            al[2] = QlS[r0o + k2c]; al[3] = QlS[r1o + k2c];
            #pragma unroll
            for (int nt = 0; nt < 8; nt++) {
                const int co = (nt*8 + qrow)*QP;
                uint32_t bb[2] = { KhS[co + k2a], KhS[co + k2c] };
                MMA_F16(sf[nt], ah, bb);
            }
            #pragma unroll
            for (int nt = 0; nt < 8; nt++) {
                const int co = (nt*8 + qrow)*QP;
                uint32_t bb[2] = { KhS[co + k2a], KhS[co + k2c] };
                MMA_F16(sf[nt], al, bb);
            }
        }

        if (kt >= 2*qi) {
            #pragma unroll
            for (int nt = 0; nt < 8; nt++) {
                #pragma unroll
                for (int i = 0; i < 4; i++) {
                    int col_g = kt*64 + nt*8 + 2*qk + (i & 1);
                    int row_g = qi*128 + wr + qrow + 8*(i >> 1);
                    if (col_g > row_g) sf[nt][i] = -1e30f;
                }
            }
        }

        #pragma unroll
        for (int nt = 0; nt < 8; nt++) {
            sf[nt][0] = ex2(sf[nt][0]);
            sf[nt][1] = ex2(sf[nt][1]);
            sf[nt][2] = ex2(sf[nt][2]);
            sf[nt][3] = ex2(sf[nt][3]);
            l0 += sf[nt][0] + sf[nt][1];
            l1 += sf[nt][2] + sf[nt][3];
        }

        #pragma unroll
        for (int kc = 0; kc < 4; kc++) {
            uint32_t pah[4], pal[4];
            float r0, r1;
            pah[0] = pack_hi16(sf[2*kc][0],   sf[2*kc][1],   r0, r1); pal[0] = pack_lo16(r0, r1);
            pah[1] = pack_hi16(sf[2*kc][2],   sf[2*kc][3],   r0, r1); pal[1] = pack_lo16(r0, r1);
            pah[2] = pack_hi16(sf[2*kc+1][0], sf[2*kc+1][1], r0, r1); pal[2] = pack_lo16(r0, r1);
            pah[3] = pack_hi16(sf[2*kc+1][2], sf[2*kc+1][3], r0, r1); pal[3] = pack_lo16(r0, r1);
            const int kpa = 8*kc + qk, kpc = kpa + 4;
            #pragma unroll
            for (int nt = 0; nt < 8; nt++) {
                const int col = nt*8 + qrow;
                uint32_t bb[2] = { VhS[kpa*VP + col], VhS[kpc*VP + col] };
                MMA_F16(of[nt], pah, bb);
            }
            #pragma unroll
            for (int nt = 0; nt < 8; nt++) {
                const int col = nt*8 + qrow;
                uint32_t bb[2] = { VhS[kpa*VP + col], VhS[kpc*VP + col] };
                MMA_F16(of[nt], pal, bb);
            }
        }

        __syncthreads();

        if (kt + 2 < nkt) {
            const int nk = kt + 2;
            uint32_t kh_d = sbase + (9216  + st*2304 + krow*QP + kk2b)*4;
            uint32_t vh_d = sbase + (13824 + st*2304 + vkp*VP + vdb)*4;
            const uint32_t* skh = kh_g + kgo + (size_t)nk*64*32;
            const uint32_t* svh = vh_g + vgo + (size_t)nk*32*64;
            CPA16(kh_d, skh);  CPA16(kh_d+16, skh+4);
            CPA16(vh_d, svh);  CPA16(vh_d+16, svh+4);
            CPA_COMMIT();
        }
    }

    l0 += __shfl_xor_sync(0xffffffffu, l0, 1);
    l0 += __shfl_xor_sync(0xffffffffu, l0, 2);
    l1 += __shfl_xor_sync(0xffffffffu, l1, 1);
    l1 += __shfl_xor_sync(0xffffffffu, l1, 2);

    float inv0 = 1.f / l0, inv1 = 1.f / l1;
    #pragma unroll
    for (int nt = 0; nt < 8; nt++) {
        const int k2g = h*32 + nt*4 + qk;
        const int chn = k2g >> 3, wix = k2g & 7;
        const int row0 = b*SS + qi*128 + wr + qrow;
        float r0, r1;
        uint32_t hv = pack_hi16(of[nt][0]*inv0, of[nt][1]*inv0, r0, r1);
        size_t di = ((size_t)chn*MROWS + row0)*8 + wix;
        cth[di] = hv;
        ctl[di] = pack_lo16(r0, r1);
        hv = pack_hi16(of[nt][2]*inv1, of[nt][3]*inv1, r0, r1);
        di = ((size_t)chn*MROWS + row0 + 8)*8 + wix;
        cth[di] = hv;
        ctl[di] = pack_lo16(r0, r1);
    }
}

// ---------------------------------------------------------------------------
extern "C" void kernel_launch(void* const* d_in, const int* in_sizes, int n_in,
                              void* d_out, int out_size)
{
    (void)in_sizes; (void)n_in; (void)out_size;
    const float* query = (const float*)d_in[0];
    const float* key   = (const float*)d_in[1];
    const float* value = (const float*)d_in[2];
    const float* Wq = (const float*)d_in[4];
    const float* bq = (const float*)d_in[5];
    const float* Wk = (const float*)d_in[6];
    const float* bk = (const float*)d_in[7];
    const float* Wv = (const float*)d_in[8];
    const float* bv = (const float*)d_in[9];
    const float* Wo = (const float*)d_in[10];
    const float* bo = (const float*)d_in[11];
    float* out = (float*)d_out;

    float *qlin, *klin, *vlin, *cosT, *sinT;
    uint32_t *qh, *ql, *kh, *vh;
    uint32_t *ah, *al, *wh, *cth, *ctl;
    cudaGetSymbolAddress((void**)&qlin, g_qlin);
    cudaGetSymbolAddress((void**)&klin, g_klin);
    cudaGetSymbolAddress((void**)&vlin, g_vlin);
    cudaGetSymbolAddress((void**)&cosT, g_cos);
    cudaGetSymbolAddress((void**)&sinT, g_sin);
    cudaGetSymbolAddress((void**)&qh, g_qh);
    cudaGetSymbolAddress((void**)&ql, g_ql);
    cudaGetSymbolAddress((void**)&kh, g_kh);
    cudaGetSymbolAddress((void**)&vh, g_vh);
    cudaGetSymbolAddress((void**)&ah, g_ah);
    cudaGetSymbolAddress((void**)&al, g_al);
    cudaGetSymbolAddress((void**)&wh, g_wh);
    cudaGetSymbolAddress((void**)&cth, g_cth);
    cudaGetSymbolAddress((void**)&ctl, g_ctl);

    const size_t ASTRIDE = (size_t)MROWS*512;
    const size_t WSTRIDE = (size_t)DD*512;

    cudaFuncSetAttribute(flash_tc6, cudaFuncAttributeMaxDynamicSharedMemorySize, FLASH_SMEM);
    cudaFuncSetAttribute(gemm_fp16b, cudaFuncAttributeMaxDynamicSharedMemorySize, GEMM_SMEM);

    rope_tables<<<SS*32/256, 256>>>(cosT, sinT);

    const int ABLK = MROWS*DD/8/256;   // 2048
    const int WBLK = DD*DD/8/256;      // 512
    dim3 sp3Grid(ABLK, 3);
    split_act3<<<sp3Grid, 256>>>(query, key, value, ah, al, ASTRIDE);
    dim3 sp4Grid(WBLK, 4);
    split_w4<<<sp4Grid, 256>>>(Wq, Wk, Wv, Wo, wh, WSTRIDE);

    GArg gq = { ah + 0*ASTRIDE, al + 0*ASTRIDE, wh + 0*WSTRIDE, bq, qlin };
    GArg gk = { ah + 1*ASTRIDE, al + 1*ASTRIDE, wh + 1*WSTRIDE, bk, klin };
    GArg gv = { ah + 2*ASTRIDE, al + 2*ASTRIDE, wh + 2*WSTRIDE, bv, vlin };
    dim3 gemmGrid(DD/128, MROWS/128, 3);
    gemm_fp16b<<<gemmGrid, 256, GEMM_SMEM>>>(gq, gk, gv);

    dim3 rsGrid((BB*HH*SS*16)/256, 2);
    rope_split<<<rsGrid, 256>>>(qlin, klin, cosT, sinT, qh, ql, kh);
    v_split<<<(BB*HH*1024*16)/256, 256>>>(vlin, vh);

    dim3 faGrid(SS/128, BB*HH);            // (16, 32)
    flash_tc6<<<faGrid, 256, FLASH_SMEM>>>(qh, ql, kh, vh, cth, ctl);

    GArg go = { cth, ctl, wh + 3*WSTRIDE, bo, out };
    dim3 gemmGridO(DD/128, MROWS/128, 1);
    gemm_fp16b<<<gemmGridO, 256, GEMM_SMEM>>>(go, go, go);
}